// round 1
// baseline (speedup 1.0000x reference)
#include <cuda_runtime.h>

// Problem dims (fixed by the reference)
#define BB 16
#define RR 1024
#define TT 512
#define DD 1024
#define HH 1024

// Scratch (allocation-free rule: __device__ globals)
__device__ float g_Rproj[BB * RR * HH];    // 67 MB
__device__ float g_Qproj[BB * TT * HH];    // 33.5 MB
__device__ float g_scores[BB * RR * TT];   // 33.5 MB (softmax in-place)
__device__ float g_att[BB * RR * DD];      // 67 MB

// ----------------------------------------------------------------------------
// Tiled SGEMM: C[M,N] = A[M,K] * B + (bias)
//   TRANS_B == false : B is [K,N] row-major  (NN)
//   TRANS_B == true  : B is [N,K] row-major  (NT, i.e. C = A * B^T)
// Tile 128x128x16, 256 threads, 8x8 microtile, all dims divisible by tiles.
// Batched via blockIdx.z with element strides sA/sB/sC.
// ----------------------------------------------------------------------------
template <bool TRANS_B, bool BIAS>
__global__ __launch_bounds__(256) void sgemm_kernel(
    const float* __restrict__ A, const float* __restrict__ B,
    const float* __restrict__ bias, float* __restrict__ C,
    int M, int N, int K, long sA, long sB, long sC)
{
    constexpr int BM = 128, BN = 128, BK = 16;

    __shared__ float As[BK][BM];      // transposed A tile: As[k][m]
    __shared__ float Bs[BK][BN];      // Bs[k][n]

    A += (long)blockIdx.z * sA;
    B += (long)blockIdx.z * sB;
    C += (long)blockIdx.z * sC;

    const int tid  = threadIdx.x;
    const int tx   = tid & 15;        // 0..15 -> 8 cols each
    const int ty   = tid >> 4;        // 0..15 -> 8 rows each
    const int row0 = blockIdx.y * BM;
    const int col0 = blockIdx.x * BN;

    float acc[8][8];
#pragma unroll
    for (int i = 0; i < 8; i++)
#pragma unroll
        for (int j = 0; j < 8; j++) acc[i][j] = 0.f;

    for (int kb = 0; kb < K; kb += BK) {
        // ---- load A tile (BM x BK) as float4 along K, scatter transposed ----
#pragma unroll
        for (int it = 0; it < 2; it++) {
            int idx  = tid + it * 256;          // 0..511
            int fRow = idx >> 2;                // 0..127
            int fK   = (idx & 3) << 2;          // 0,4,8,12
            float4 a = *(const float4*)&A[(long)(row0 + fRow) * K + kb + fK];
            As[fK + 0][fRow] = a.x;
            As[fK + 1][fRow] = a.y;
            As[fK + 2][fRow] = a.z;
            As[fK + 3][fRow] = a.w;
        }
        // ---- load B tile ----
        if (!TRANS_B) {
#pragma unroll
            for (int it = 0; it < 2; it++) {
                int idx = tid + it * 256;       // 0..511
                int fK  = idx >> 5;             // 0..15
                int fN  = (idx & 31) << 2;      // 0..124
                float4 b = *(const float4*)&B[(long)(kb + fK) * N + col0 + fN];
                *(float4*)&Bs[fK][fN] = b;
            }
        } else {
#pragma unroll
            for (int it = 0; it < 2; it++) {
                int idx  = tid + it * 256;      // 0..511
                int fN   = idx >> 2;            // 0..127
                int fK   = (idx & 3) << 2;      // 0,4,8,12
                float4 b = *(const float4*)&B[(long)(col0 + fN) * K + kb + fK];
                Bs[fK + 0][fN] = b.x;
                Bs[fK + 1][fN] = b.y;
                Bs[fK + 2][fN] = b.z;
                Bs[fK + 3][fN] = b.w;
            }
        }
        __syncthreads();

        // ---- compute ----
#pragma unroll
        for (int k = 0; k < BK; k++) {
            float4 a0 = *(const float4*)&As[k][ty * 8];
            float4 a1 = *(const float4*)&As[k][ty * 8 + 4];
            float4 b0 = *(const float4*)&Bs[k][tx * 8];
            float4 b1 = *(const float4*)&Bs[k][tx * 8 + 4];
            float ra[8] = {a0.x, a0.y, a0.z, a0.w, a1.x, a1.y, a1.z, a1.w};
            float rb[8] = {b0.x, b0.y, b0.z, b0.w, b1.x, b1.y, b1.z, b1.w};
#pragma unroll
            for (int i = 0; i < 8; i++)
#pragma unroll
                for (int j = 0; j < 8; j++) acc[i][j] += ra[i] * rb[j];
        }
        __syncthreads();
    }

    // ---- epilogue ----
    float4 bv0 = make_float4(0.f, 0.f, 0.f, 0.f), bv1 = bv0;
    if (BIAS) {
        bv0 = *(const float4*)&bias[col0 + tx * 8];
        bv1 = *(const float4*)&bias[col0 + tx * 8 + 4];
    }
#pragma unroll
    for (int i = 0; i < 8; i++) {
        long cr = (long)(row0 + ty * 8 + i) * N + col0 + tx * 8;
        float4 c0 = make_float4(acc[i][0] + bv0.x, acc[i][1] + bv0.y,
                                acc[i][2] + bv0.z, acc[i][3] + bv0.w);
        float4 c1 = make_float4(acc[i][4] + bv1.x, acc[i][5] + bv1.y,
                                acc[i][6] + bv1.z, acc[i][7] + bv1.w);
        *(float4*)&C[cr]     = c0;
        *(float4*)&C[cr + 4] = c1;
    }
}

// ----------------------------------------------------------------------------
// Softmax over rows of length TT=512 (in place). 128 threads, float4 each.
// ----------------------------------------------------------------------------
__global__ __launch_bounds__(128) void softmax_rows(float* __restrict__ data)
{
    __shared__ float smax[4];
    __shared__ float ssum[4];
    const long row = blockIdx.x;
    float4* p = (float4*)(data + row * TT);
    const int tid  = threadIdx.x;
    const int lane = tid & 31, warp = tid >> 5;

    float4 v = p[tid];
    float m = fmaxf(fmaxf(v.x, v.y), fmaxf(v.z, v.w));
#pragma unroll
    for (int o = 16; o > 0; o >>= 1) m = fmaxf(m, __shfl_xor_sync(0xffffffffu, m, o));
    if (lane == 0) smax[warp] = m;
    __syncthreads();
    m = fmaxf(fmaxf(smax[0], smax[1]), fmaxf(smax[2], smax[3]));

    v.x = expf(v.x - m); v.y = expf(v.y - m);
    v.z = expf(v.z - m); v.w = expf(v.w - m);
    float s = v.x + v.y + v.z + v.w;
#pragma unroll
    for (int o = 16; o > 0; o >>= 1) s += __shfl_xor_sync(0xffffffffu, s, o);
    if (lane == 0) ssum[warp] = s;
    __syncthreads();
    s = ssum[0] + ssum[1] + ssum[2] + ssum[3];

    const float inv = 1.0f / s;
    v.x *= inv; v.y *= inv; v.z *= inv; v.w *= inv;
    p[tid] = v;
}

// ----------------------------------------------------------------------------
// Final: out[row] = sum_d region*Ws1 + att*Ws2 + region*att*Ws3, + bs.
// One block (256 threads, 1 float4 each) per (b,r) row.
// ----------------------------------------------------------------------------
__global__ __launch_bounds__(256) void final_reduce(
    const float* __restrict__ region, const float* __restrict__ att,
    const float* __restrict__ Ws, const float* __restrict__ bs,
    float* __restrict__ out)
{
    __shared__ float red[8];
    const long row = blockIdx.x;
    const int tid  = threadIdx.x;
    const int lane = tid & 31, warp = tid >> 5;

    float4 r  = ((const float4*)(region + row * DD))[tid];
    float4 a  = ((const float4*)(att    + row * DD))[tid];
    float4 w1 = ((const float4*)(Ws           ))[tid];
    float4 w2 = ((const float4*)(Ws +     DD  ))[tid];
    float4 w3 = ((const float4*)(Ws + 2 * DD  ))[tid];

    float s = r.x * w1.x + a.x * w2.x + r.x * a.x * w3.x
            + r.y * w1.y + a.y * w2.y + r.y * a.y * w3.y
            + r.z * w1.z + a.z * w2.z + r.z * a.z * w3.z
            + r.w * w1.w + a.w * w2.w + r.w * a.w * w3.w;

#pragma unroll
    for (int o = 16; o > 0; o >>= 1) s += __shfl_xor_sync(0xffffffffu, s, o);
    if (lane == 0) red[warp] = s;
    __syncthreads();
    if (warp == 0) {
        float t = (lane < 8) ? red[lane] : 0.f;
#pragma unroll
        for (int o = 4; o > 0; o >>= 1) t += __shfl_xor_sync(0xffffffffu, t, o);
        if (lane == 0) out[row] = t + bs[0];
    }
}

// ----------------------------------------------------------------------------
extern "C" void kernel_launch(void* const* d_in, const int* in_sizes, int n_in,
                              void* d_out, int out_size)
{
    (void)in_sizes; (void)n_in; (void)out_size;
    const float* region = (const float*)d_in[0];  // [B,R,D]
    const float* query  = (const float*)d_in[1];  // [B,T,D]
    const float* Wr     = (const float*)d_in[2];  // [D,H]
    const float* br     = (const float*)d_in[3];  // [H]
    const float* Wq     = (const float*)d_in[4];  // [D,H]
    const float* bq     = (const float*)d_in[5];  // [H]
    const float* Ws     = (const float*)d_in[6];  // [3D,1]
    const float* bs     = (const float*)d_in[7];  // [1]
    float* out = (float*)d_out;                   // [B,R]

    float *Rproj, *Qproj, *scores, *att;
    cudaGetSymbolAddress((void**)&Rproj,  g_Rproj);
    cudaGetSymbolAddress((void**)&Qproj,  g_Qproj);
    cudaGetSymbolAddress((void**)&scores, g_scores);
    cudaGetSymbolAddress((void**)&att,    g_att);

    // 1) R_proj = region @ Wr + br   (M=16384, N=1024, K=1024)
    sgemm_kernel<false, true><<<dim3(HH / 128, (BB * RR) / 128, 1), 256>>>(
        region, Wr, br, Rproj, BB * RR, HH, DD, 0, 0, 0);

    // 2) Q_proj = query @ Wq + bq    (M=8192, N=1024, K=1024)
    sgemm_kernel<false, true><<<dim3(HH / 128, (BB * TT) / 128, 1), 256>>>(
        query, Wq, bq, Qproj, BB * TT, HH, DD, 0, 0, 0);

    // 3) scores[b] = R_proj[b] @ Q_proj[b]^T   (M=R, N=T, K=H, batched)
    sgemm_kernel<true, false><<<dim3(TT / 128, RR / 128, BB), 256>>>(
        Rproj, Qproj, nullptr, scores, RR, TT, HH,
        (long)RR * HH, (long)TT * HH, (long)RR * TT);

    // 4) softmax over T (in place)
    softmax_rows<<<BB * RR, 128>>>(scores);

    // 5) attended[b] = attn[b] @ query[b]   (M=R, N=D, K=T, batched)
    sgemm_kernel<false, false><<<dim3(DD / 128, RR / 128, BB), 256>>>(
        scores, query, nullptr, att, RR, DD, TT,
        (long)RR * TT, (long)TT * DD, (long)RR * DD);

    // 6) combine + project to scalar per (b,r)
    final_reduce<<<BB * RR, 256>>>(region, att, Ws, bs, out);
}

// round 3
// speedup vs baseline: 2.4836x; 2.4836x over previous
#include <cuda_runtime.h>
#include <cuda_bf16.h>
#include <cstdint>

#define BB 16
#define RR 1024
#define TT 512
#define DD 1024
#define HH 1024

typedef __nv_bfloat16 bf16;

// ---------------------------------------------------------------------------
// Scratch (__device__ globals; allocation-free rule)
// ---------------------------------------------------------------------------
__device__ bf16 g_region_h[BB*RR*DD], g_region_l[BB*RR*DD];
__device__ bf16 g_query_h [BB*TT*DD], g_query_l [BB*TT*DD];
__device__ bf16 g_Wr_h[DD*HH], g_Wr_l[DD*HH];
__device__ bf16 g_Wq_h[DD*HH], g_Wq_l[DD*HH];
__device__ bf16 g_Mt_h[DD*DD], g_Mt_l[DD*DD];          // Mt[d'][d] = sum_h Wq[d',h]Wr[d,h]
__device__ bf16 g_P_h[BB*RR*DD], g_P_l[BB*RR*DD];      // P = region @ Mt^T
__device__ bf16 g_qT_h[BB*DD*TT], g_qT_l[BB*DD*TT];    // query transposed [B][D][T]
__device__ bf16 g_attn_h[BB*RR*TT], g_attn_l[BB*RR*TT];
__device__ float g_scores[BB*RR*TT];
__device__ float g_att[BB*RR*DD];
__device__ float g_u[BB*RR];
__device__ float g_v[BB*TT];
__device__ float g_wrbq[DD];
__device__ float g_wqbr[DD];
__device__ float g_c[1];

// ---------------------------------------------------------------------------
// PTX helpers (sm_80-compatible: works on compute_103 virtual arch)
// ---------------------------------------------------------------------------
__device__ __forceinline__ uint32_t smem_u32(const void* p) {
    uint32_t a;
    asm("{ .reg .u64 t; cvta.to.shared.u64 t, %1; cvt.u32.u64 %0, t; }" : "=r"(a) : "l"(p));
    return a;
}
#define CP_ASYNC16(dst, src) \
    asm volatile("cp.async.cg.shared.global [%0], [%1], 16;" :: "r"(dst), "l"(src))
#define CP_COMMIT() asm volatile("cp.async.commit_group;" ::: "memory")
#define CP_WAIT1()  asm volatile("cp.async.wait_group 1;" ::: "memory")
#define CP_WAIT0()  asm volatile("cp.async.wait_group 0;" ::: "memory")

__device__ __forceinline__ void ldsm4(uint32_t* r, uint32_t addr) {
    asm volatile("ldmatrix.sync.aligned.m8n8.x4.shared.b16 {%0,%1,%2,%3}, [%4];"
                 : "=r"(r[0]), "=r"(r[1]), "=r"(r[2]), "=r"(r[3]) : "r"(addr));
}
__device__ __forceinline__ void mma16816(float* d, const uint32_t* a, const uint32_t* b) {
    asm volatile("mma.sync.aligned.m16n8k16.row.col.f32.bf16.bf16.f32 "
                 "{%0,%1,%2,%3}, {%4,%5,%6,%7}, {%8,%9}, {%0,%1,%2,%3};"
                 : "+f"(d[0]), "+f"(d[1]), "+f"(d[2]), "+f"(d[3])
                 : "r"(a[0]), "r"(a[1]), "r"(a[2]), "r"(a[3]), "r"(b[0]), "r"(b[1]));
}

// ---------------------------------------------------------------------------
// bf16x3 GEMM: C[M,N] = sum over 3 phases { Ah*Bh^T, Ah*Bl^T, Al*Bh^T }.
// A [M,K] row-major, B [N,K] row-major (NT). Block 128x128, BK=32,
// 4 warps (warp tile 64x64), ldmatrix + mma.m16n8k16, 2-stage cp.async.
// EPI: 0 = fp32 store; 1 = bf16 hi/lo split store; 2 = fp32 + u[m] + v[n].
// Batched via blockIdx.z.
// Smem rows padded to 80B (32 bf16 + 16B pad) -> ldmatrix conflict-free.
// ---------------------------------------------------------------------------
#define STAGE_B 20480   // (128 rows * 80B) * 2 tiles (A + B)

template <int EPI>
__global__ __launch_bounds__(128, 2) void gemm3_bf16(
    const bf16* __restrict__ Ah, const bf16* __restrict__ Al,
    const bf16* __restrict__ Bh, const bf16* __restrict__ Bl,
    float* __restrict__ Cf, bf16* __restrict__ Chi, bf16* __restrict__ Clo,
    const float* __restrict__ uvec, const float* __restrict__ vvec,
    int Kbase, int lda, int ldb, int ldc,
    long sA, long sB, long sC, int uStr, int vStr)
{
    __shared__ __align__(1024) uint8_t smem_raw[2 * STAGE_B];
    const int tid = threadIdx.x;
    const int wid = tid >> 5, l = tid & 31;
    const int wm = wid >> 1, wn = wid & 1;
    const int blockM = blockIdx.y * 128, blockN = blockIdx.x * 128;
    const int z = blockIdx.z;

    Ah += (long)z * sA;  Al += (long)z * sA;
    Bh += (long)z * sB;  Bl += (long)z * sB;

    const uint32_t smBase = smem_u32(smem_raw);
    const int cpb = Kbase / 32;
    const int NK  = 3 * cpb;

    // ldmatrix per-lane base addresses
    // A: lanes 0-15 -> rows m0+l (k+0 half); 16-31 -> rows m0+l-16 (k+8 half)
    const uint32_t aF = smBase +
        (uint32_t)((wm * 64 + (l & 15)) * 80 + ((l >> 4) * 16));
    // B: n-row = (l&7) + (l>=16 ? 8 : 0), k-half = (l>>3)&1
    const int bn = (l & 7) + ((l & 16) >> 1);
    const uint32_t bF = smBase + 10240u +
        (uint32_t)((wn * 64 + bn) * 80 + (((l >> 3) & 1) * 16));

    float acc[4][8][4];
#pragma unroll
    for (int i = 0; i < 4; i++)
#pragma unroll
        for (int j = 0; j < 8; j++)
#pragma unroll
            for (int q = 0; q < 4; q++) acc[i][j][q] = 0.f;

    const int lr = tid >> 2, lj = tid & 3;   // loader: row group, 16B chunk

    auto load_stage = [&](int stage, int kb) {
        const int ph  = kb / cpb;
        const int kbl = kb - ph * cpb;
        const bf16* Ap = (ph < 2) ? Ah : Al;
        const bf16* Bp = (ph == 1) ? Bl : Bh;
        const int k0 = kbl * 32;
        const uint32_t sa = smBase + stage * STAGE_B;
        const uint32_t sb = sa + 10240u;
#pragma unroll
        for (int it = 0; it < 4; it++) {
            const int rr = lr + it * 32;
            const bf16* ga = Ap + (long)(blockM + rr) * lda + k0 + lj * 8;
            CP_ASYNC16(sa + (uint32_t)(rr * 80 + lj * 16), ga);
            const bf16* gb = Bp + (long)(blockN + rr) * ldb + k0 + lj * 8;
            CP_ASYNC16(sb + (uint32_t)(rr * 80 + lj * 16), gb);
        }
        CP_COMMIT();
    };

    load_stage(0, 0);
    for (int kb = 0; kb < NK; kb++) {
        if (kb + 1 < NK) { load_stage((kb + 1) & 1, kb + 1); CP_WAIT1(); }
        else             { CP_WAIT0(); }
        __syncthreads();
        const uint32_t so = (uint32_t)(kb & 1) * STAGE_B;
#pragma unroll
        for (int ks = 0; ks < 2; ks++) {
            uint32_t af[4][4], bfr[4][4];
#pragma unroll
            for (int i = 0; i < 4; i++)
                ldsm4(af[i], aF + so + (uint32_t)(i * (16 * 80) + ks * 32));
#pragma unroll
            for (int j = 0; j < 4; j++)
                ldsm4(bfr[j], bF + so + (uint32_t)(j * (16 * 80) + ks * 32));
#pragma unroll
            for (int i = 0; i < 4; i++)
#pragma unroll
                for (int j = 0; j < 4; j++) {
                    mma16816(acc[i][2 * j],     af[i], &bfr[j][0]);
                    mma16816(acc[i][2 * j + 1], af[i], &bfr[j][2]);
                }
        }
        __syncthreads();
    }

    // ---- epilogue ----
    const int gid = l >> 2, tig = l & 3;
#pragma unroll
    for (int i = 0; i < 4; i++) {
        const int r0g = blockM + wm * 64 + 16 * i + gid;
        const int r1g = r0g + 8;
        float um0 = 0.f, um1 = 0.f;
        if (EPI == 2) {
            um0 = uvec[(long)z * uStr + r0g];
            um1 = uvec[(long)z * uStr + r1g];
        }
#pragma unroll
        for (int jj = 0; jj < 8; jj++) {
            const int c0 = blockN + wn * 64 + 8 * jj + 2 * tig;
            float x0 = acc[i][jj][0], x1 = acc[i][jj][1];
            float x2 = acc[i][jj][2], x3 = acc[i][jj][3];
            if (EPI == 2) {
                float2 vv = *(const float2*)&vvec[(long)z * vStr + c0];
                x0 += um0 + vv.x;  x1 += um0 + vv.y;
                x2 += um1 + vv.x;  x3 += um1 + vv.y;
            }
            if (EPI == 0 || EPI == 2) {
                float* base = Cf + (long)z * sC;
                *(float2*)&base[(long)r0g * ldc + c0] = make_float2(x0, x1);
                *(float2*)&base[(long)r1g * ldc + c0] = make_float2(x2, x3);
            } else {
                bf16 h0 = __float2bfloat16_rn(x0), h1 = __float2bfloat16_rn(x1);
                bf16 h2 = __float2bfloat16_rn(x2), h3 = __float2bfloat16_rn(x3);
                bf16 l0 = __float2bfloat16_rn(x0 - __bfloat162float(h0));
                bf16 l1 = __float2bfloat16_rn(x1 - __bfloat162float(h1));
                bf16 l2 = __float2bfloat16_rn(x2 - __bfloat162float(h2));
                bf16 l3 = __float2bfloat16_rn(x3 - __bfloat162float(h3));
                bf16* bh = Chi + (long)z * sC;
                bf16* bl = Clo + (long)z * sC;
                *(__nv_bfloat162*)&bh[(long)r0g * ldc + c0] = __halves2bfloat162(h0, h1);
                *(__nv_bfloat162*)&bh[(long)r1g * ldc + c0] = __halves2bfloat162(h2, h3);
                *(__nv_bfloat162*)&bl[(long)r0g * ldc + c0] = __halves2bfloat162(l0, l1);
                *(__nv_bfloat162*)&bl[(long)r1g * ldc + c0] = __halves2bfloat162(l2, l3);
            }
        }
    }
}

// ---------------------------------------------------------------------------
// Elementwise float -> bf16 hi/lo split
// ---------------------------------------------------------------------------
__global__ __launch_bounds__(256) void split_bf16(
    const float* __restrict__ in, bf16* __restrict__ h, bf16* __restrict__ lo, long n4)
{
    long i = (long)blockIdx.x * blockDim.x + threadIdx.x;
    if (i >= n4) return;
    float4 v = ((const float4*)in)[i];
    bf16 h0 = __float2bfloat16_rn(v.x), h1 = __float2bfloat16_rn(v.y);
    bf16 h2 = __float2bfloat16_rn(v.z), h3 = __float2bfloat16_rn(v.w);
    bf16 l0 = __float2bfloat16_rn(v.x - __bfloat162float(h0));
    bf16 l1 = __float2bfloat16_rn(v.y - __bfloat162float(h1));
    bf16 l2 = __float2bfloat16_rn(v.z - __bfloat162float(h2));
    bf16 l3 = __float2bfloat16_rn(v.w - __bfloat162float(h3));
    ((__nv_bfloat162*)h )[2 * i]     = __halves2bfloat162(h0, h1);
    ((__nv_bfloat162*)h )[2 * i + 1] = __halves2bfloat162(h2, h3);
    ((__nv_bfloat162*)lo)[2 * i]     = __halves2bfloat162(l0, l1);
    ((__nv_bfloat162*)lo)[2 * i + 1] = __halves2bfloat162(l2, l3);
}

// query [B][T][D] f32 -> queryT hi/lo [B][D][T] bf16
__global__ __launch_bounds__(256) void transpose_split(
    const float* __restrict__ in, bf16* __restrict__ oh, bf16* __restrict__ ol)
{
    __shared__ float s[32][33];
    const float* ib = in + (long)blockIdx.z * TT * DD;
    bf16* oh_b = oh + (long)blockIdx.z * DD * TT;
    bf16* ol_b = ol + (long)blockIdx.z * DD * TT;
    const int d0 = blockIdx.x * 32, t0 = blockIdx.y * 32;
    const int tx = threadIdx.x, ty = threadIdx.y;
#pragma unroll
    for (int i = 0; i < 32; i += 8)
        s[ty + i][tx] = ib[(long)(t0 + ty + i) * DD + d0 + tx];
    __syncthreads();
#pragma unroll
    for (int i = 0; i < 32; i += 8) {
        float v = s[tx][ty + i];
        bf16 h = __float2bfloat16_rn(v);
        long o = (long)(d0 + ty + i) * TT + t0 + tx;
        oh_b[o] = h;
        ol_b[o] = __float2bfloat16_rn(v - __bfloat162float(h));
    }
}

// out[row] = dot(X[row,:], w) (+ cadd[0]); one warp per row
__global__ void rowdot(const float* __restrict__ X, const float* __restrict__ w,
                       const float* __restrict__ cadd, float* __restrict__ out,
                       int ld, long nRows)
{
    long row = (long)blockIdx.x * (blockDim.x >> 5) + (threadIdx.x >> 5);
    if (row >= nRows) return;
    const int lane = threadIdx.x & 31;
    const float* x = X + row * ld;
    float s = 0.f;
    for (int k = lane; k < ld; k += 32) s += x[k] * w[k];
#pragma unroll
    for (int o = 16; o > 0; o >>= 1) s += __shfl_xor_sync(0xffffffffu, s, o);
    if (lane == 0) out[row] = s + (cadd ? cadd[0] : 0.f);
}

// softmax over T=512, write attn as bf16 hi/lo
__global__ __launch_bounds__(128) void softmax_split(
    const float* __restrict__ sc, bf16* __restrict__ ah, bf16* __restrict__ al)
{
    __shared__ float smax[4];
    __shared__ float ssum[4];
    const long row = blockIdx.x;
    const float4* p = (const float4*)(sc + row * TT);
    const int tid = threadIdx.x;
    const int lane = tid & 31, warp = tid >> 5;

    float4 v = p[tid];
    float m = fmaxf(fmaxf(v.x, v.y), fmaxf(v.z, v.w));
#pragma unroll
    for (int o = 16; o > 0; o >>= 1) m = fmaxf(m, __shfl_xor_sync(0xffffffffu, m, o));
    if (lane == 0) smax[warp] = m;
    __syncthreads();
    m = fmaxf(fmaxf(smax[0], smax[1]), fmaxf(smax[2], smax[3]));

    v.x = expf(v.x - m); v.y = expf(v.y - m);
    v.z = expf(v.z - m); v.w = expf(v.w - m);
    float s = v.x + v.y + v.z + v.w;
#pragma unroll
    for (int o = 16; o > 0; o >>= 1) s += __shfl_xor_sync(0xffffffffu, s, o);
    if (lane == 0) ssum[warp] = s;
    __syncthreads();
    s = ssum[0] + ssum[1] + ssum[2] + ssum[3];

    const float inv = 1.0f / s;
    v.x *= inv; v.y *= inv; v.z *= inv; v.w *= inv;

    bf16 h0 = __float2bfloat16_rn(v.x), h1 = __float2bfloat16_rn(v.y);
    bf16 h2 = __float2bfloat16_rn(v.z), h3 = __float2bfloat16_rn(v.w);
    bf16 l0 = __float2bfloat16_rn(v.x - __bfloat162float(h0));
    bf16 l1 = __float2bfloat16_rn(v.y - __bfloat162float(h1));
    bf16 l2 = __float2bfloat16_rn(v.z - __bfloat162float(h2));
    bf16 l3 = __float2bfloat16_rn(v.w - __bfloat162float(h3));
    ((__nv_bfloat162*)(ah + row * TT))[2 * tid]     = __halves2bfloat162(h0, h1);
    ((__nv_bfloat162*)(ah + row * TT))[2 * tid + 1] = __halves2bfloat162(h2, h3);
    ((__nv_bfloat162*)(al + row * TT))[2 * tid]     = __halves2bfloat162(l0, l1);
    ((__nv_bfloat162*)(al + row * TT))[2 * tid + 1] = __halves2bfloat162(l2, l3);
}

// out[row] = sum_d region*Ws1 + att*Ws2 + region*att*Ws3, + bs
__global__ __launch_bounds__(256) void final_reduce(
    const float* __restrict__ region, const float* __restrict__ att,
    const float* __restrict__ Ws, const float* __restrict__ bs,
    float* __restrict__ out)
{
    __shared__ float red[8];
    const long row = blockIdx.x;
    const int tid = threadIdx.x;
    const int lane = tid & 31, warp = tid >> 5;

    float4 r  = ((const float4*)(region + row * DD))[tid];
    float4 a  = ((const float4*)(att    + row * DD))[tid];
    float4 w1 = ((const float4*)(Ws          ))[tid];
    float4 w2 = ((const float4*)(Ws +     DD ))[tid];
    float4 w3 = ((const float4*)(Ws + 2 * DD ))[tid];

    float s = r.x * w1.x + a.x * w2.x + r.x * a.x * w3.x
            + r.y * w1.y + a.y * w2.y + r.y * a.y * w3.y
            + r.z * w1.z + a.z * w2.z + r.z * a.z * w3.z
            + r.w * w1.w + a.w * w2.w + r.w * a.w * w3.w;

#pragma unroll
    for (int o = 16; o > 0; o >>= 1) s += __shfl_xor_sync(0xffffffffu, s, o);
    if (lane == 0) red[warp] = s;
    __syncthreads();
    if (warp == 0) {
        float t = (lane < 8) ? red[lane] : 0.f;
#pragma unroll
        for (int o = 4; o > 0; o >>= 1) t += __shfl_xor_sync(0xffffffffu, t, o);
        if (lane == 0) out[row] = t + bs[0];
    }
}

// ---------------------------------------------------------------------------
extern "C" void kernel_launch(void* const* d_in, const int* in_sizes, int n_in,
                              void* d_out, int out_size)
{
    (void)in_sizes; (void)n_in; (void)out_size;
    const float* region = (const float*)d_in[0];  // [B,R,D]
    const float* query  = (const float*)d_in[1];  // [B,T,D]
    const float* Wr     = (const float*)d_in[2];  // [D,H]
    const float* br     = (const float*)d_in[3];  // [H]
    const float* Wq     = (const float*)d_in[4];  // [D,H]
    const float* bq     = (const float*)d_in[5];  // [H]
    const float* Ws     = (const float*)d_in[6];  // [3D,1]
    const float* bs     = (const float*)d_in[7];  // [1]
    float* out = (float*)d_out;                   // [B,R]

    bf16 *region_h, *region_l, *query_h, *query_l;
    bf16 *Wr_h, *Wr_l, *Wq_h, *Wq_l, *Mt_h, *Mt_l, *P_h, *P_l;
    bf16 *qT_h, *qT_l, *attn_h, *attn_l;
    float *scores, *att, *u, *v, *wrbq, *wqbr, *cptr;
    cudaGetSymbolAddress((void**)&region_h, g_region_h);
    cudaGetSymbolAddress((void**)&region_l, g_region_l);
    cudaGetSymbolAddress((void**)&query_h,  g_query_h);
    cudaGetSymbolAddress((void**)&query_l,  g_query_l);
    cudaGetSymbolAddress((void**)&Wr_h, g_Wr_h);
    cudaGetSymbolAddress((void**)&Wr_l, g_Wr_l);
    cudaGetSymbolAddress((void**)&Wq_h, g_Wq_h);
    cudaGetSymbolAddress((void**)&Wq_l, g_Wq_l);
    cudaGetSymbolAddress((void**)&Mt_h, g_Mt_h);
    cudaGetSymbolAddress((void**)&Mt_l, g_Mt_l);
    cudaGetSymbolAddress((void**)&P_h,  g_P_h);
    cudaGetSymbolAddress((void**)&P_l,  g_P_l);
    cudaGetSymbolAddress((void**)&qT_h, g_qT_h);
    cudaGetSymbolAddress((void**)&qT_l, g_qT_l);
    cudaGetSymbolAddress((void**)&attn_h, g_attn_h);
    cudaGetSymbolAddress((void**)&attn_l, g_attn_l);
    cudaGetSymbolAddress((void**)&scores, g_scores);
    cudaGetSymbolAddress((void**)&att,    g_att);
    cudaGetSymbolAddress((void**)&u,      g_u);
    cudaGetSymbolAddress((void**)&v,      g_v);
    cudaGetSymbolAddress((void**)&wrbq,   g_wrbq);
    cudaGetSymbolAddress((void**)&wqbr,   g_wqbr);
    cudaGetSymbolAddress((void**)&cptr,   g_c);

    // 0) splits
    split_bf16<<<(unsigned)(((long)BB*RR*DD/4 + 255)/256), 256>>>(region, region_h, region_l, (long)BB*RR*DD/4);
    split_bf16<<<(unsigned)(((long)BB*TT*DD/4 + 255)/256), 256>>>(query, query_h, query_l, (long)BB*TT*DD/4);
    split_bf16<<<(unsigned)(((long)DD*HH/4 + 255)/256), 256>>>(Wr, Wr_h, Wr_l, (long)DD*HH/4);
    split_bf16<<<(unsigned)(((long)DD*HH/4 + 255)/256), 256>>>(Wq, Wq_h, Wq_l, (long)DD*HH/4);
    transpose_split<<<dim3(DD/32, TT/32, BB), dim3(32, 8)>>>(query, qT_h, qT_l);

    // bias rank-1 terms
    rowdot<<<1, 32>>>(br, bq, nullptr, cptr, HH, 1);                       // c = br.bq
    rowdot<<<DD/8, 256>>>(Wr, bq, nullptr, wrbq, HH, DD);                  // Wr @ bq
    rowdot<<<DD/8, 256>>>(Wq, br, nullptr, wqbr, HH, DD);                  // Wq @ br
    rowdot<<<(BB*RR)/8, 256>>>(region, wrbq, cptr, u, DD, (long)BB*RR);    // u = region.wrbq + c
    rowdot<<<(BB*TT)/8, 256>>>(query, wqbr, nullptr, v, DD, (long)BB*TT);  // v = query.wqbr

    // 1) Mt = Wq @ Wr^T  (split out)  M=N=1024, K=1024
    gemm3_bf16<1><<<dim3(8, 8, 1), 128>>>(
        Wq_h, Wq_l, Wr_h, Wr_l, nullptr, Mt_h, Mt_l, nullptr, nullptr,
        HH, HH, HH, DD, 0, 0, 0, 0, 0);

    // 2) P = region @ Mt^T  (split out)  M=16384, N=1024, K=1024
    gemm3_bf16<1><<<dim3(8, 128, 1), 128>>>(
        region_h, region_l, Mt_h, Mt_l, nullptr, P_h, P_l, nullptr, nullptr,
        DD, DD, DD, DD, 0, 0, 0, 0, 0);

    // 3) scores[b] = P[b] @ query[b]^T + u + v   M=1024, N=512, K=1024
    gemm3_bf16<2><<<dim3(4, 8, BB), 128>>>(
        P_h, P_l, query_h, query_l, scores, nullptr, nullptr, u, v,
        DD, DD, DD, TT, (long)RR*DD, (long)TT*DD, (long)RR*TT, RR, TT);

    // 4) softmax -> attn hi/lo
    softmax_split<<<BB*RR, 128>>>(scores, attn_h, attn_l);

    // 5) att[b] = attn[b] @ queryT[b]^T   M=1024, N=1024, K=512
    gemm3_bf16<0><<<dim3(8, 8, BB), 128>>>(
        attn_h, attn_l, qT_h, qT_l, att, nullptr, nullptr, nullptr, nullptr,
        TT, TT, TT, DD, (long)RR*TT, (long)DD*TT, (long)RR*DD, 0, 0);

    // 6) combine + project
    final_reduce<<<BB*RR, 256>>>(region, att, Ws, bs, out);
}

// round 6
// speedup vs baseline: 3.1413x; 1.2648x over previous
#include <cuda_runtime.h>
#include <cuda_bf16.h>
#include <cstdint>

#define BB 16
#define RR 1024
#define TT 512
#define DD 1024
#define HH 1024

typedef __nv_bfloat16 bf16;

// ---------------------------------------------------------------------------
// Scratch (__device__ globals; allocation-free rule)
// ---------------------------------------------------------------------------
__device__ bf16 g_region_h[BB*RR*DD], g_region_l[BB*RR*DD];
__device__ bf16 g_query_h [BB*TT*DD], g_query_l [BB*TT*DD];
__device__ bf16 g_Wr_h[DD*HH], g_Wr_l[DD*HH];
__device__ bf16 g_Wq_h[DD*HH], g_Wq_l[DD*HH];
__device__ bf16 g_Mt_h[DD*DD], g_Mt_l[DD*DD];        // Mt2[d][d'] = sum_h Wr[d,h]Wq[d',h]
__device__ bf16 g_Qp_h[BB*TT*DD], g_Qp_l[BB*TT*DD];  // Qp = query @ Mt2^T
__device__ bf16 g_qT_h[BB*DD*TT], g_qT_l[BB*DD*TT];  // query transposed [B][D][T]
__device__ bf16 g_attn_h[BB*RR*TT], g_attn_l[BB*RR*TT];
__device__ float g_scores[BB*RR*TT];
__device__ float g_att[BB*RR*DD];
__device__ float g_u[BB*RR];
__device__ float g_v[BB*TT];
__device__ float g_wrbq[DD];
__device__ float g_wqbr[DD];
__device__ float g_c[1];

// ---------------------------------------------------------------------------
// PTX helpers (sm_80-compatible; compiles for compute_103 virtual arch)
// ---------------------------------------------------------------------------
__device__ __forceinline__ uint32_t smem_u32(const void* p) {
    uint32_t a;
    asm("{ .reg .u64 t; cvta.to.shared.u64 t, %1; cvt.u32.u64 %0, t; }" : "=r"(a) : "l"(p));
    return a;
}
#define CP_ASYNC16(dst, src) \
    asm volatile("cp.async.cg.shared.global [%0], [%1], 16;" :: "r"(dst), "l"(src))
#define CP_COMMIT() asm volatile("cp.async.commit_group;" ::: "memory")
#define CP_WAIT2()  asm volatile("cp.async.wait_group 2;" ::: "memory")
#define CP_WAIT1()  asm volatile("cp.async.wait_group 1;" ::: "memory")
#define CP_WAIT0()  asm volatile("cp.async.wait_group 0;" ::: "memory")

__device__ __forceinline__ void ldsm4(uint32_t* r, uint32_t addr) {
    asm volatile("ldmatrix.sync.aligned.m8n8.x4.shared.b16 {%0,%1,%2,%3}, [%4];"
                 : "=r"(r[0]), "=r"(r[1]), "=r"(r[2]), "=r"(r[3]) : "r"(addr));
}
__device__ __forceinline__ void mma16816(float* d, const uint32_t* a, const uint32_t* b) {
    asm volatile("mma.sync.aligned.m16n8k16.row.col.f32.bf16.bf16.f32 "
                 "{%0,%1,%2,%3}, {%4,%5,%6,%7}, {%8,%9}, {%0,%1,%2,%3};"
                 : "+f"(d[0]), "+f"(d[1]), "+f"(d[2]), "+f"(d[3])
                 : "r"(a[0]), "r"(a[1]), "r"(a[2]), "r"(a[3]), "r"(b[0]), "r"(b[1]));
}

// ---------------------------------------------------------------------------
// bf16x3 GEMM: C[M,N] = sum over 3 phases { Ah*Bh^T, Ah*Bl^T, Al*Bh^T }.
// A [M,K] row-major, B [N,K] row-major (NT). Block 128x128, BK=32,
// 4 warps (64x64 warp tile), ldmatrix + mma.m16n8k16.
// 4-stage cp.async pipeline, one __syncthreads per K-iteration.
// EPI: 0 = fp32 store; 1 = bf16 hi/lo split store; 2 = fp32 + u[m] + v[n].
// ---------------------------------------------------------------------------
#define STAGE_B 20480           // (128 rows * 80B padded) * 2 tiles (A + B)
#define NSTAGE  4
#define SMEM_GEMM (NSTAGE * STAGE_B)   // 80 KB dynamic

template <int EPI>
__global__ __launch_bounds__(128, 2) void gemm3_bf16(
    const bf16* __restrict__ Ah, const bf16* __restrict__ Al,
    const bf16* __restrict__ Bh, const bf16* __restrict__ Bl,
    float* __restrict__ Cf, bf16* __restrict__ Chi, bf16* __restrict__ Clo,
    const float* __restrict__ uvec, const float* __restrict__ vvec,
    int Kbase, int lda, int ldb, int ldc,
    long sA, long sB, long sC, int uStr, int vStr)
{
    extern __shared__ __align__(16) uint8_t smem_raw[];
    const int tid = threadIdx.x;
    const int wid = tid >> 5, l = tid & 31;
    const int wm = wid >> 1, wn = wid & 1;
    const int blockM = blockIdx.y * 128, blockN = blockIdx.x * 128;
    const int z = blockIdx.z;

    Ah += (long)z * sA;  Al += (long)z * sA;
    Bh += (long)z * sB;  Bl += (long)z * sB;

    const uint32_t smBase = smem_u32(smem_raw);
    const int cpb = Kbase / 32;
    const int NK  = 3 * cpb;

    // ldmatrix per-lane base addresses (80B-padded rows: conflict-free)
    const uint32_t aF = smBase +
        (uint32_t)((wm * 64 + (l & 15)) * 80 + ((l >> 4) * 16));
    const int bn = (l & 7) + ((l & 16) >> 1);
    const uint32_t bF = smBase + 10240u +
        (uint32_t)((wn * 64 + bn) * 80 + (((l >> 3) & 1) * 16));

    float acc[4][8][4];
#pragma unroll
    for (int i = 0; i < 4; i++)
#pragma unroll
        for (int j = 0; j < 8; j++)
#pragma unroll
            for (int q = 0; q < 4; q++) acc[i][j][q] = 0.f;

    const int lr = tid >> 2, lj = tid & 3;

    auto load_stage = [&](int stage, int kb) {
        const int ph  = kb / cpb;
        const int kbl = kb - ph * cpb;
        const bf16* Ap = (ph < 2) ? Ah : Al;
        const bf16* Bp = (ph == 1) ? Bl : Bh;
        const int k0 = kbl * 32;
        const uint32_t sa = smBase + stage * STAGE_B;
        const uint32_t sb = sa + 10240u;
#pragma unroll
        for (int it = 0; it < 4; it++) {
            const int rr = lr + it * 32;
            const bf16* ga = Ap + (long)(blockM + rr) * lda + k0 + lj * 8;
            CP_ASYNC16(sa + (uint32_t)(rr * 80 + lj * 16), ga);
            const bf16* gb = Bp + (long)(blockN + rr) * ldb + k0 + lj * 8;
            CP_ASYNC16(sb + (uint32_t)(rr * 80 + lj * 16), gb);
        }
        CP_COMMIT();
    };

    load_stage(0, 0);
    load_stage(1, 1);
    load_stage(2, 2);

    for (int kb = 0; kb < NK; kb++) {
        if (kb < NK - 2)      CP_WAIT2();
        else if (kb == NK - 2) CP_WAIT1();
        else                   CP_WAIT0();
        __syncthreads();
        if (kb + 3 < NK) load_stage((kb + 3) & 3, kb + 3);

        const uint32_t so = (uint32_t)(kb & 3) * STAGE_B;
#pragma unroll
        for (int ks = 0; ks < 2; ks++) {
            uint32_t af[4][4], bfr[4][4];
#pragma unroll
            for (int i = 0; i < 4; i++)
                ldsm4(af[i], aF + so + (uint32_t)(i * (16 * 80) + ks * 32));
#pragma unroll
            for (int j = 0; j < 4; j++)
                ldsm4(bfr[j], bF + so + (uint32_t)(j * (16 * 80) + ks * 32));
#pragma unroll
            for (int i = 0; i < 4; i++)
#pragma unroll
                for (int j = 0; j < 4; j++) {
                    mma16816(acc[i][2 * j],     af[i], &bfr[j][0]);
                    mma16816(acc[i][2 * j + 1], af[i], &bfr[j][2]);
                }
        }
    }

    // ---- epilogue ----
    const int gid = l >> 2, tig = l & 3;
#pragma unroll
    for (int i = 0; i < 4; i++) {
        const int r0g = blockM + wm * 64 + 16 * i + gid;
        const int r1g = r0g + 8;
        float um0 = 0.f, um1 = 0.f;
        if (EPI == 2) {
            um0 = uvec[(long)z * uStr + r0g];
            um1 = uvec[(long)z * uStr + r1g];
        }
#pragma unroll
        for (int jj = 0; jj < 8; jj++) {
            const int c0 = blockN + wn * 64 + 8 * jj + 2 * tig;
            float x0 = acc[i][jj][0], x1 = acc[i][jj][1];
            float x2 = acc[i][jj][2], x3 = acc[i][jj][3];
            if (EPI == 2) {
                float2 vv = *(const float2*)&vvec[(long)z * vStr + c0];
                x0 += um0 + vv.x;  x1 += um0 + vv.y;
                x2 += um1 + vv.x;  x3 += um1 + vv.y;
            }
            if (EPI == 0 || EPI == 2) {
                float* base = Cf + (long)z * sC;
                *(float2*)&base[(long)r0g * ldc + c0] = make_float2(x0, x1);
                *(float2*)&base[(long)r1g * ldc + c0] = make_float2(x2, x3);
            } else {
                bf16 h0 = __float2bfloat16_rn(x0), h1 = __float2bfloat16_rn(x1);
                bf16 h2 = __float2bfloat16_rn(x2), h3 = __float2bfloat16_rn(x3);
                bf16 l0 = __float2bfloat16_rn(x0 - __bfloat162float(h0));
                bf16 l1 = __float2bfloat16_rn(x1 - __bfloat162float(h1));
                bf16 l2 = __float2bfloat16_rn(x2 - __bfloat162float(h2));
                bf16 l3 = __float2bfloat16_rn(x3 - __bfloat162float(h3));
                bf16* bh = Chi + (long)z * sC;
                bf16* bl = Clo + (long)z * sC;
                *(__nv_bfloat162*)&bh[(long)r0g * ldc + c0] = __halves2bfloat162(h0, h1);
                *(__nv_bfloat162*)&bh[(long)r1g * ldc + c0] = __halves2bfloat162(h2, h3);
                *(__nv_bfloat162*)&bl[(long)r0g * ldc + c0] = __halves2bfloat162(l0, l1);
                *(__nv_bfloat162*)&bl[(long)r1g * ldc + c0] = __halves2bfloat162(l2, l3);
            }
        }
    }
}

// ---------------------------------------------------------------------------
// Small kernels
// ---------------------------------------------------------------------------
__global__ __launch_bounds__(256) void split_bf16(
    const float* __restrict__ in, bf16* __restrict__ h, bf16* __restrict__ lo, long n4)
{
    long i = (long)blockIdx.x * blockDim.x + threadIdx.x;
    if (i >= n4) return;
    float4 v = ((const float4*)in)[i];
    bf16 h0 = __float2bfloat16_rn(v.x), h1 = __float2bfloat16_rn(v.y);
    bf16 h2 = __float2bfloat16_rn(v.z), h3 = __float2bfloat16_rn(v.w);
    bf16 l0 = __float2bfloat16_rn(v.x - __bfloat162float(h0));
    bf16 l1 = __float2bfloat16_rn(v.y - __bfloat162float(h1));
    bf16 l2 = __float2bfloat16_rn(v.z - __bfloat162float(h2));
    bf16 l3 = __float2bfloat16_rn(v.w - __bfloat162float(h3));
    ((__nv_bfloat162*)h )[2 * i]     = __halves2bfloat162(h0, h1);
    ((__nv_bfloat162*)h )[2 * i + 1] = __halves2bfloat162(h2, h3);
    ((__nv_bfloat162*)lo)[2 * i]     = __halves2bfloat162(l0, l1);
    ((__nv_bfloat162*)lo)[2 * i + 1] = __halves2bfloat162(l2, l3);
}

__global__ __launch_bounds__(256) void transpose_split(
    const float* __restrict__ in, bf16* __restrict__ oh, bf16* __restrict__ ol)
{
    __shared__ float s[32][33];
    const float* ib = in + (long)blockIdx.z * TT * DD;
    bf16* oh_b = oh + (long)blockIdx.z * DD * TT;
    bf16* ol_b = ol + (long)blockIdx.z * DD * TT;
    const int d0 = blockIdx.x * 32, t0 = blockIdx.y * 32;
    const int tx = threadIdx.x, ty = threadIdx.y;
#pragma unroll
    for (int i = 0; i < 32; i += 8)
        s[ty + i][tx] = ib[(long)(t0 + ty + i) * DD + d0 + tx];
    __syncthreads();
#pragma unroll
    for (int i = 0; i < 32; i += 8) {
        float v = s[tx][ty + i];
        bf16 h = __float2bfloat16_rn(v);
        long o = (long)(d0 + ty + i) * TT + t0 + tx;
        oh_b[o] = h;
        ol_b[o] = __float2bfloat16_rn(v - __bfloat162float(h));
    }
}

__global__ void rowdot(const float* __restrict__ X, const float* __restrict__ w,
                       const float* __restrict__ cadd, float* __restrict__ out,
                       int ld, long nRows)
{
    long row = (long)blockIdx.x * (blockDim.x >> 5) + (threadIdx.x >> 5);
    if (row >= nRows) return;
    const int lane = threadIdx.x & 31;
    const float* x = X + row * ld;
    float s = 0.f;
    for (int k = lane; k < ld; k += 32) s += x[k] * w[k];
#pragma unroll
    for (int o = 16; o > 0; o >>= 1) s += __shfl_xor_sync(0xffffffffu, s, o);
    if (lane == 0) out[row] = s + (cadd ? cadd[0] : 0.f);
}

__global__ __launch_bounds__(128) void softmax_split(
    const float* __restrict__ sc, bf16* __restrict__ ah, bf16* __restrict__ al)
{
    __shared__ float smax[4];
    __shared__ float ssum[4];
    const long row = blockIdx.x;
    const float4* p = (const float4*)(sc + row * TT);
    const int tid = threadIdx.x;
    const int lane = tid & 31, warp = tid >> 5;

    float4 v = p[tid];
    float m = fmaxf(fmaxf(v.x, v.y), fmaxf(v.z, v.w));
#pragma unroll
    for (int o = 16; o > 0; o >>= 1) m = fmaxf(m, __shfl_xor_sync(0xffffffffu, m, o));
    if (lane == 0) smax[warp] = m;
    __syncthreads();
    m = fmaxf(fmaxf(smax[0], smax[1]), fmaxf(smax[2], smax[3]));

    v.x = expf(v.x - m); v.y = expf(v.y - m);
    v.z = expf(v.z - m); v.w = expf(v.w - m);
    float s = v.x + v.y + v.z + v.w;
#pragma unroll
    for (int o = 16; o > 0; o >>= 1) s += __shfl_xor_sync(0xffffffffu, s, o);
    if (lane == 0) ssum[warp] = s;
    __syncthreads();
    s = ssum[0] + ssum[1] + ssum[2] + ssum[3];

    const float inv = 1.0f / s;
    v.x *= inv; v.y *= inv; v.z *= inv; v.w *= inv;

    bf16 h0 = __float2bfloat16_rn(v.x), h1 = __float2bfloat16_rn(v.y);
    bf16 h2 = __float2bfloat16_rn(v.z), h3 = __float2bfloat16_rn(v.w);
    bf16 l0 = __float2bfloat16_rn(v.x - __bfloat162float(h0));
    bf16 l1 = __float2bfloat16_rn(v.y - __bfloat162float(h1));
    bf16 l2 = __float2bfloat16_rn(v.z - __bfloat162float(h2));
    bf16 l3 = __float2bfloat16_rn(v.w - __bfloat162float(h3));
    ((__nv_bfloat162*)(ah + row * TT))[2 * tid]     = __halves2bfloat162(h0, h1);
    ((__nv_bfloat162*)(ah + row * TT))[2 * tid + 1] = __halves2bfloat162(h2, h3);
    ((__nv_bfloat162*)(al + row * TT))[2 * tid]     = __halves2bfloat162(l0, l1);
    ((__nv_bfloat162*)(al + row * TT))[2 * tid + 1] = __halves2bfloat162(l2, l3);
}

__global__ __launch_bounds__(256) void final_reduce(
    const float* __restrict__ region, const float* __restrict__ att,
    const float* __restrict__ Ws, const float* __restrict__ bs,
    float* __restrict__ out)
{
    __shared__ float red[8];
    const long row = blockIdx.x;
    const int tid = threadIdx.x;
    const int lane = tid & 31, warp = tid >> 5;

    float4 r  = ((const float4*)(region + row * DD))[tid];
    float4 a  = ((const float4*)(att    + row * DD))[tid];
    float4 w1 = ((const float4*)(Ws          ))[tid];
    float4 w2 = ((const float4*)(Ws +     DD ))[tid];
    float4 w3 = ((const float4*)(Ws + 2 * DD ))[tid];

    float s = r.x * w1.x + a.x * w2.x + r.x * a.x * w3.x
            + r.y * w1.y + a.y * w2.y + r.y * a.y * w3.y
            + r.z * w1.z + a.z * w2.z + r.z * a.z * w3.z
            + r.w * w1.w + a.w * w2.w + r.w * a.w * w3.w;

#pragma unroll
    for (int o = 16; o > 0; o >>= 1) s += __shfl_xor_sync(0xffffffffu, s, o);
    if (lane == 0) red[warp] = s;
    __syncthreads();
    if (warp == 0) {
        float t = (lane < 8) ? red[lane] : 0.f;
#pragma unroll
        for (int o = 4; o > 0; o >>= 1) t += __shfl_xor_sync(0xffffffffu, t, o);
        if (lane == 0) out[row] = t + bs[0];
    }
}

// ---------------------------------------------------------------------------
extern "C" void kernel_launch(void* const* d_in, const int* in_sizes, int n_in,
                              void* d_out, int out_size)
{
    (void)in_sizes; (void)n_in; (void)out_size;
    const float* region = (const float*)d_in[0];
    const float* query  = (const float*)d_in[1];
    const float* Wr     = (const float*)d_in[2];
    const float* br     = (const float*)d_in[3];
    const float* Wq     = (const float*)d_in[4];
    const float* bq     = (const float*)d_in[5];
    const float* Ws     = (const float*)d_in[6];
    const float* bs     = (const float*)d_in[7];
    float* out = (float*)d_out;

    bf16 *region_h, *region_l, *query_h, *query_l;
    bf16 *Wr_h, *Wr_l, *Wq_h, *Wq_l, *Mt_h, *Mt_l, *Qp_h, *Qp_l;
    bf16 *qT_h, *qT_l, *attn_h, *attn_l;
    float *scores, *att, *u, *v, *wrbq, *wqbr, *cptr;
    cudaGetSymbolAddress((void**)&region_h, g_region_h);
    cudaGetSymbolAddress((void**)&region_l, g_region_l);
    cudaGetSymbolAddress((void**)&query_h,  g_query_h);
    cudaGetSymbolAddress((void**)&query_l,  g_query_l);
    cudaGetSymbolAddress((void**)&Wr_h, g_Wr_h);
    cudaGetSymbolAddress((void**)&Wr_l, g_Wr_l);
    cudaGetSymbolAddress((void**)&Wq_h, g_Wq_h);
    cudaGetSymbolAddress((void**)&Wq_l, g_Wq_l);
    cudaGetSymbolAddress((void**)&Mt_h, g_Mt_h);
    cudaGetSymbolAddress((void**)&Mt_l, g_Mt_l);
    cudaGetSymbolAddress((void**)&Qp_h, g_Qp_h);
    cudaGetSymbolAddress((void**)&Qp_l, g_Qp_l);
    cudaGetSymbolAddress((void**)&qT_h, g_qT_h);
    cudaGetSymbolAddress((void**)&qT_l, g_qT_l);
    cudaGetSymbolAddress((void**)&attn_h, g_attn_h);
    cudaGetSymbolAddress((void**)&attn_l, g_attn_l);
    cudaGetSymbolAddress((void**)&scores, g_scores);
    cudaGetSymbolAddress((void**)&att,    g_att);
    cudaGetSymbolAddress((void**)&u,      g_u);
    cudaGetSymbolAddress((void**)&v,      g_v);
    cudaGetSymbolAddress((void**)&wrbq,   g_wrbq);
    cudaGetSymbolAddress((void**)&wqbr,   g_wqbr);
    cudaGetSymbolAddress((void**)&cptr,   g_c);

    cudaFuncSetAttribute(gemm3_bf16<0>, cudaFuncAttributeMaxDynamicSharedMemorySize, SMEM_GEMM);
    cudaFuncSetAttribute(gemm3_bf16<1>, cudaFuncAttributeMaxDynamicSharedMemorySize, SMEM_GEMM);
    cudaFuncSetAttribute(gemm3_bf16<2>, cudaFuncAttributeMaxDynamicSharedMemorySize, SMEM_GEMM);

    // splits first so the Qp GEMM is the 6th launch (ncu -s 5 captures it)
    split_bf16<<<(unsigned)(((long)DD*HH/4 + 255)/256), 256>>>(Wr, Wr_h, Wr_l, (long)DD*HH/4);
    split_bf16<<<(unsigned)(((long)DD*HH/4 + 255)/256), 256>>>(Wq, Wq_h, Wq_l, (long)DD*HH/4);
    split_bf16<<<(unsigned)(((long)BB*TT*DD/4 + 255)/256), 256>>>(query, query_h, query_l, (long)BB*TT*DD/4);
    split_bf16<<<(unsigned)(((long)BB*RR*DD/4 + 255)/256), 256>>>(region, region_h, region_l, (long)BB*RR*DD/4);

    // 1) Mt2 = Wr @ Wq^T  (split out)  M=N=1024, K=1024
    gemm3_bf16<1><<<dim3(8, 8, 1), 128, SMEM_GEMM>>>(
        Wr_h, Wr_l, Wq_h, Wq_l, nullptr, Mt_h, Mt_l, nullptr, nullptr,
        HH, HH, HH, DD, 0, 0, 0, 0, 0);

    // 2) Qp[b] = query[b] @ Mt2^T  (split out)  M=512, N=1024, K=1024, batched
    gemm3_bf16<1><<<dim3(8, 4, BB), 128, SMEM_GEMM>>>(
        query_h, query_l, Mt_h, Mt_l, nullptr, Qp_h, Qp_l, nullptr, nullptr,
        DD, DD, DD, DD, (long)TT*DD, 0, (long)TT*DD, 0, 0);

    // remaining prep
    transpose_split<<<dim3(DD/32, TT/32, BB), dim3(32, 8)>>>(query, qT_h, qT_l);
    rowdot<<<1, 32>>>(br, bq, nullptr, cptr, HH, 1);
    rowdot<<<DD/8, 256>>>(Wr, bq, nullptr, wrbq, HH, DD);
    rowdot<<<DD/8, 256>>>(Wq, br, nullptr, wqbr, HH, DD);
    rowdot<<<(BB*RR)/8, 256>>>(region, wrbq, cptr, u, DD, (long)BB*RR);
    rowdot<<<(BB*TT)/8, 256>>>(query, wqbr, nullptr, v, DD, (long)BB*TT);

    // 3) scores[b] = region[b] @ Qp[b]^T + u + v   M=1024, N=512, K=1024
    gemm3_bf16<2><<<dim3(4, 8, BB), 128, SMEM_GEMM>>>(
        region_h, region_l, Qp_h, Qp_l, scores, nullptr, nullptr, u, v,
        DD, DD, DD, TT, (long)RR*DD, (long)TT*DD, (long)RR*TT, RR, TT);

    // 4) softmax -> attn hi/lo
    softmax_split<<<BB*RR, 128>>>(scores, attn_h, attn_l);

    // 5) att[b] = attn[b] @ queryT[b]^T   M=1024, N=1024, K=512
    gemm3_bf16<0><<<dim3(8, 8, BB), 128, SMEM_GEMM>>>(
        attn_h, attn_l, qT_h, qT_l, att, nullptr, nullptr, nullptr, nullptr,
        TT, TT, TT, DD, (long)RR*TT, (long)DD*TT, (long)RR*DD, 0, 0);

    // 6) combine + project
    final_reduce<<<BB*RR, 256>>>(region, att, Ws, bs, out);
}

// round 8
// speedup vs baseline: 3.3671x; 1.0719x over previous
#include <cuda_runtime.h>
#include <cuda_bf16.h>
#include <cstdint>

#define BB 16
#define RR 1024
#define TT 512
#define DD 1024
#define HH 1024

typedef __nv_bfloat16 bf16;

// ---------------------------------------------------------------------------
// Scratch (__device__ globals; allocation-free rule)
// ---------------------------------------------------------------------------
__device__ bf16 g_region_h[BB*RR*DD], g_region_l[BB*RR*DD];
__device__ bf16 g_query_h [BB*TT*DD], g_query_l [BB*TT*DD];
__device__ bf16 g_Wr_h[DD*HH], g_Wr_l[DD*HH];
__device__ bf16 g_Wq_h[DD*HH], g_Wq_l[DD*HH];
__device__ bf16 g_Mt_h[DD*DD], g_Mt_l[DD*DD];        // Mt2 = Wr @ Wq^T
__device__ bf16 g_Qp_h[BB*TT*DD], g_Qp_l[BB*TT*DD];  // Qp = query @ Mt2^T
__device__ bf16 g_qT_h[BB*DD*TT], g_qT_l[BB*DD*TT];  // query^T [B][D][T]
__device__ bf16 g_attn_h[BB*RR*TT], g_attn_l[BB*RR*TT];
__device__ float g_scores[BB*RR*TT];
__device__ float g_u[BB*RR];
__device__ float g_v[BB*TT];
__device__ float g_wrbq[DD];
__device__ float g_wqbr[DD];
__device__ float g_c[1];

// ---------------------------------------------------------------------------
// PTX helpers (sm_80-compatible; compiles for compute_103 virtual arch)
// ---------------------------------------------------------------------------
__device__ __forceinline__ uint32_t smem_u32(const void* p) {
    uint32_t a;
    asm("{ .reg .u64 t; cvta.to.shared.u64 t, %1; cvt.u32.u64 %0, t; }" : "=r"(a) : "l"(p));
    return a;
}
#define CP_ASYNC16(dst, src) \
    asm volatile("cp.async.cg.shared.global [%0], [%1], 16;" :: "r"(dst), "l"(src))
#define CP_COMMIT() asm volatile("cp.async.commit_group;" ::: "memory")
#define CP_WAIT2()  asm volatile("cp.async.wait_group 2;" ::: "memory")
#define CP_WAIT1()  asm volatile("cp.async.wait_group 1;" ::: "memory")
#define CP_WAIT0()  asm volatile("cp.async.wait_group 0;" ::: "memory")

__device__ __forceinline__ void ldsm4(uint32_t* r, uint32_t addr) {
    asm volatile("ldmatrix.sync.aligned.m8n8.x4.shared.b16 {%0,%1,%2,%3}, [%4];"
                 : "=r"(r[0]), "=r"(r[1]), "=r"(r[2]), "=r"(r[3]) : "r"(addr));
}
__device__ __forceinline__ void mma16816(float* d, const uint32_t* a, const uint32_t* b) {
    asm volatile("mma.sync.aligned.m16n8k16.row.col.f32.bf16.bf16.f32 "
                 "{%0,%1,%2,%3}, {%4,%5,%6,%7}, {%8,%9}, {%0,%1,%2,%3};"
                 : "+f"(d[0]), "+f"(d[1]), "+f"(d[2]), "+f"(d[3])
                 : "r"(a[0]), "r"(a[1]), "r"(a[2]), "r"(a[3]), "r"(b[0]), "r"(b[1]));
}

// ---------------------------------------------------------------------------
// bf16x3 GEMM: C[M,N] = sum over 3 phases { Ah*Bh^T, Ah*Bl^T, Al*Bh^T }.
// Block 128x128, BK=32, 4 warps (64x64 warp tile), 4-stage cp.async.
// EPI: 1 = bf16 hi/lo split store; 2 = fp32 + u[m] + v[n];
//      3 = fused scorer: atomicAdd per-row  sum_c C*(Ws2[c]+region[r,c]*Ws3[c]).
// ---------------------------------------------------------------------------
#define STAGE_B 20480           // (128 rows * 80B padded) * 2 tiles (A + B)
#define NSTAGE  4
#define SMEM_GEMM (NSTAGE * STAGE_B)   // 80 KB dynamic

template <int EPI>
__global__ __launch_bounds__(128, 2) void gemm3_bf16(
    const bf16* __restrict__ Ah, const bf16* __restrict__ Al,
    const bf16* __restrict__ Bh, const bf16* __restrict__ Bl,
    float* __restrict__ Cf, bf16* __restrict__ Chi, bf16* __restrict__ Clo,
    const float* __restrict__ uvec, const float* __restrict__ vvec,
    const float* __restrict__ regionF, const float* __restrict__ WsP,
    float* __restrict__ outP,
    int Kbase, int lda, int ldb, int ldc,
    long sA, long sB, long sC, int uStr, int vStr)
{
    extern __shared__ __align__(16) uint8_t smem_raw[];
    const int tid = threadIdx.x;
    const int wid = tid >> 5, l = tid & 31;
    const int wm = wid >> 1, wn = wid & 1;
    const int blockM = blockIdx.y * 128, blockN = blockIdx.x * 128;
    const int z = blockIdx.z;

    Ah += (long)z * sA;  Al += (long)z * sA;
    Bh += (long)z * sB;  Bl += (long)z * sB;

    const uint32_t smBase = smem_u32(smem_raw);
    const int cpb = Kbase / 32;
    const int NK  = 3 * cpb;

    const uint32_t aF = smBase +
        (uint32_t)((wm * 64 + (l & 15)) * 80 + ((l >> 4) * 16));
    const int bn = (l & 7) + ((l & 16) >> 1);
    const uint32_t bF = smBase + 10240u +
        (uint32_t)((wn * 64 + bn) * 80 + (((l >> 3) & 1) * 16));

    float acc[4][8][4];
#pragma unroll
    for (int i = 0; i < 4; i++)
#pragma unroll
        for (int j = 0; j < 8; j++)
#pragma unroll
            for (int q = 0; q < 4; q++) acc[i][j][q] = 0.f;

    const int lr = tid >> 2, lj = tid & 3;

    auto load_stage = [&](int stage, int kb) {
        const int ph  = kb / cpb;
        const int kbl = kb - ph * cpb;
        const bf16* Ap = (ph < 2) ? Ah : Al;
        const bf16* Bp = (ph == 1) ? Bl : Bh;
        const int k0 = kbl * 32;
        const uint32_t sa = smBase + stage * STAGE_B;
        const uint32_t sb = sa + 10240u;
#pragma unroll
        for (int it = 0; it < 4; it++) {
            const int rr = lr + it * 32;
            const bf16* ga = Ap + (long)(blockM + rr) * lda + k0 + lj * 8;
            CP_ASYNC16(sa + (uint32_t)(rr * 80 + lj * 16), ga);
            const bf16* gb = Bp + (long)(blockN + rr) * ldb + k0 + lj * 8;
            CP_ASYNC16(sb + (uint32_t)(rr * 80 + lj * 16), gb);
        }
        CP_COMMIT();
    };

    load_stage(0, 0);
    load_stage(1, 1);
    load_stage(2, 2);

    for (int kb = 0; kb < NK; kb++) {
        if (kb < NK - 2)       CP_WAIT2();
        else if (kb == NK - 2) CP_WAIT1();
        else                   CP_WAIT0();
        __syncthreads();
        if (kb + 3 < NK) load_stage((kb + 3) & 3, kb + 3);

        const uint32_t so = (uint32_t)(kb & 3) * STAGE_B;
#pragma unroll
        for (int ks = 0; ks < 2; ks++) {
            uint32_t af[4][4], bfr[4][4];
#pragma unroll
            for (int i = 0; i < 4; i++)
                ldsm4(af[i], aF + so + (uint32_t)(i * (16 * 80) + ks * 32));
#pragma unroll
            for (int j = 0; j < 4; j++)
                ldsm4(bfr[j], bF + so + (uint32_t)(j * (16 * 80) + ks * 32));
#pragma unroll
            for (int i = 0; i < 4; i++)
#pragma unroll
                for (int j = 0; j < 4; j++) {
                    mma16816(acc[i][2 * j],     af[i], &bfr[j][0]);
                    mma16816(acc[i][2 * j + 1], af[i], &bfr[j][2]);
                }
        }
    }

    // ---- epilogue ----
    const int gid = l >> 2, tig = l & 3;
#pragma unroll
    for (int i = 0; i < 4; i++) {
        const int r0g = blockM + wm * 64 + 16 * i + gid;
        const int r1g = r0g + 8;
        float um0 = 0.f, um1 = 0.f;
        if (EPI == 2) {
            um0 = uvec[(long)z * uStr + r0g];
            um1 = uvec[(long)z * uStr + r1g];
        }
        float part0 = 0.f, part1 = 0.f;   // EPI==3 accumulators
#pragma unroll
        for (int jj = 0; jj < 8; jj++) {
            const int c0 = blockN + wn * 64 + 8 * jj + 2 * tig;
            float x0 = acc[i][jj][0], x1 = acc[i][jj][1];
            float x2 = acc[i][jj][2], x3 = acc[i][jj][3];
            if (EPI == 2) {
                float2 vv = *(const float2*)&vvec[(long)z * vStr + c0];
                x0 += um0 + vv.x;  x1 += um0 + vv.y;
                x2 += um1 + vv.x;  x3 += um1 + vv.y;
                float* base = Cf + (long)z * sC;
                *(float2*)&base[(long)r0g * ldc + c0] = make_float2(x0, x1);
                *(float2*)&base[(long)r1g * ldc + c0] = make_float2(x2, x3);
            } else if (EPI == 1) {
                bf16 h0 = __float2bfloat16_rn(x0), h1 = __float2bfloat16_rn(x1);
                bf16 h2 = __float2bfloat16_rn(x2), h3 = __float2bfloat16_rn(x3);
                bf16 l0 = __float2bfloat16_rn(x0 - __bfloat162float(h0));
                bf16 l1 = __float2bfloat16_rn(x1 - __bfloat162float(h1));
                bf16 l2 = __float2bfloat16_rn(x2 - __bfloat162float(h2));
                bf16 l3 = __float2bfloat16_rn(x3 - __bfloat162float(h3));
                bf16* bh = Chi + (long)z * sC;
                bf16* bl = Clo + (long)z * sC;
                *(__nv_bfloat162*)&bh[(long)r0g * ldc + c0] = __halves2bfloat162(h0, h1);
                *(__nv_bfloat162*)&bh[(long)r1g * ldc + c0] = __halves2bfloat162(h2, h3);
                *(__nv_bfloat162*)&bl[(long)r0g * ldc + c0] = __halves2bfloat162(l0, l1);
                *(__nv_bfloat162*)&bl[(long)r1g * ldc + c0] = __halves2bfloat162(l2, l3);
            } else { // EPI == 3 : fused scorer
                const float* rgB = regionF + (long)z * RR * DD;
                float2 w2 = *(const float2*)&WsP[DD + c0];
                float2 w3 = *(const float2*)&WsP[2 * DD + c0];
                float2 r0v = *(const float2*)&rgB[(long)r0g * DD + c0];
                float2 r1v = *(const float2*)&rgB[(long)r1g * DD + c0];
                part0 += x0 * (w2.x + r0v.x * w3.x) + x1 * (w2.y + r0v.y * w3.y);
                part1 += x2 * (w2.x + r1v.x * w3.x) + x3 * (w2.y + r1v.y * w3.y);
            }
        }
        if (EPI == 3) {
            // reduce over the 4 lanes of the quad (same rows, different cols)
            part0 += __shfl_xor_sync(0xffffffffu, part0, 1);
            part0 += __shfl_xor_sync(0xffffffffu, part0, 2);
            part1 += __shfl_xor_sync(0xffffffffu, part1, 1);
            part1 += __shfl_xor_sync(0xffffffffu, part1, 2);
            if (tig == 0) {
                atomicAdd(&outP[(long)z * RR + r0g], part0);
                atomicAdd(&outP[(long)z * RR + r1g], part1);
            }
        }
    }
}

// ---------------------------------------------------------------------------
// Fused prep kernels
// ---------------------------------------------------------------------------
__global__ __launch_bounds__(256) void split_bf16(
    const float* __restrict__ in, bf16* __restrict__ h, bf16* __restrict__ lo, long n4)
{
    long i = (long)blockIdx.x * blockDim.x + threadIdx.x;
    if (i >= n4) return;
    float4 v = ((const float4*)in)[i];
    bf16 h0 = __float2bfloat16_rn(v.x), h1 = __float2bfloat16_rn(v.y);
    bf16 h2 = __float2bfloat16_rn(v.z), h3 = __float2bfloat16_rn(v.w);
    bf16 l0 = __float2bfloat16_rn(v.x - __bfloat162float(h0));
    bf16 l1 = __float2bfloat16_rn(v.y - __bfloat162float(h1));
    bf16 l2 = __float2bfloat16_rn(v.z - __bfloat162float(h2));
    bf16 l3 = __float2bfloat16_rn(v.w - __bfloat162float(h3));
    ((__nv_bfloat162*)h )[2 * i]     = __halves2bfloat162(h0, h1);
    ((__nv_bfloat162*)h )[2 * i + 1] = __halves2bfloat162(h2, h3);
    ((__nv_bfloat162*)lo)[2 * i]     = __halves2bfloat162(l0, l1);
    ((__nv_bfloat162*)lo)[2 * i + 1] = __halves2bfloat162(l2, l3);
}

// per-row: split region -> h/l, u[row] = region.wrbq + c, out[row] = region.Ws1 + bs
__global__ __launch_bounds__(256) void prep_region(
    const float* __restrict__ region, const float* __restrict__ wrbq,
    const float* __restrict__ cptr, const float* __restrict__ Ws,
    const float* __restrict__ bs,
    bf16* __restrict__ rh, bf16* __restrict__ rl,
    float* __restrict__ u, float* __restrict__ outp)
{
    __shared__ float redA[8], redB[8];
    const long row = blockIdx.x;
    const int tid = threadIdx.x, lane = tid & 31, warp = tid >> 5;

    float4 v = ((const float4*)(region + row * DD))[tid];
    bf16 h0 = __float2bfloat16_rn(v.x), h1 = __float2bfloat16_rn(v.y);
    bf16 h2 = __float2bfloat16_rn(v.z), h3 = __float2bfloat16_rn(v.w);
    bf16 l0 = __float2bfloat16_rn(v.x - __bfloat162float(h0));
    bf16 l1 = __float2bfloat16_rn(v.y - __bfloat162float(h1));
    bf16 l2 = __float2bfloat16_rn(v.z - __bfloat162float(h2));
    bf16 l3 = __float2bfloat16_rn(v.w - __bfloat162float(h3));
    ((__nv_bfloat162*)(rh + row * DD))[2 * tid]     = __halves2bfloat162(h0, h1);
    ((__nv_bfloat162*)(rh + row * DD))[2 * tid + 1] = __halves2bfloat162(h2, h3);
    ((__nv_bfloat162*)(rl + row * DD))[2 * tid]     = __halves2bfloat162(l0, l1);
    ((__nv_bfloat162*)(rl + row * DD))[2 * tid + 1] = __halves2bfloat162(l2, l3);

    float4 w  = ((const float4*)wrbq)[tid];
    float4 w1 = ((const float4*)Ws  )[tid];
    float du = v.x * w.x  + v.y * w.y  + v.z * w.z  + v.w * w.w;
    float dn = v.x * w1.x + v.y * w1.y + v.z * w1.z + v.w * w1.w;
#pragma unroll
    for (int o = 16; o > 0; o >>= 1) {
        du += __shfl_xor_sync(0xffffffffu, du, o);
        dn += __shfl_xor_sync(0xffffffffu, dn, o);
    }
    if (lane == 0) { redA[warp] = du; redB[warp] = dn; }
    __syncthreads();
    if (tid == 0) {
        float su = 0.f, sn = 0.f;
#pragma unroll
        for (int k = 0; k < 8; k++) { su += redA[k]; sn += redB[k]; }
        u[row]    = su + cptr[0];
        outp[row] = sn + bs[0];
    }
}

// per-row: split query -> h/l, v[row] = query.wqbr
__global__ __launch_bounds__(256) void prep_query(
    const float* __restrict__ query, const float* __restrict__ wqbr,
    bf16* __restrict__ qh, bf16* __restrict__ ql, float* __restrict__ vvec)
{
    __shared__ float red[8];
    const long row = blockIdx.x;
    const int tid = threadIdx.x, lane = tid & 31, warp = tid >> 5;

    float4 v = ((const float4*)(query + row * DD))[tid];
    bf16 h0 = __float2bfloat16_rn(v.x), h1 = __float2bfloat16_rn(v.y);
    bf16 h2 = __float2bfloat16_rn(v.z), h3 = __float2bfloat16_rn(v.w);
    bf16 l0 = __float2bfloat16_rn(v.x - __bfloat162float(h0));
    bf16 l1 = __float2bfloat16_rn(v.y - __bfloat162float(h1));
    bf16 l2 = __float2bfloat16_rn(v.z - __bfloat162float(h2));
    bf16 l3 = __float2bfloat16_rn(v.w - __bfloat162float(h3));
    ((__nv_bfloat162*)(qh + row * DD))[2 * tid]     = __halves2bfloat162(h0, h1);
    ((__nv_bfloat162*)(qh + row * DD))[2 * tid + 1] = __halves2bfloat162(h2, h3);
    ((__nv_bfloat162*)(ql + row * DD))[2 * tid]     = __halves2bfloat162(l0, l1);
    ((__nv_bfloat162*)(ql + row * DD))[2 * tid + 1] = __halves2bfloat162(l2, l3);

    float4 w = ((const float4*)wqbr)[tid];
    float d = v.x * w.x + v.y * w.y + v.z * w.z + v.w * w.w;
#pragma unroll
    for (int o = 16; o > 0; o >>= 1) d += __shfl_xor_sync(0xffffffffu, d, o);
    if (lane == 0) red[warp] = d;
    __syncthreads();
    if (tid == 0) {
        float s = 0.f;
#pragma unroll
        for (int k = 0; k < 8; k++) s += red[k];
        vvec[row] = s;
    }
}

__global__ __launch_bounds__(256) void transpose_split(
    const float* __restrict__ in, bf16* __restrict__ oh, bf16* __restrict__ ol)
{
    __shared__ float s[32][33];
    const float* ib = in + (long)blockIdx.z * TT * DD;
    bf16* oh_b = oh + (long)blockIdx.z * DD * TT;
    bf16* ol_b = ol + (long)blockIdx.z * DD * TT;
    const int d0 = blockIdx.x * 32, t0 = blockIdx.y * 32;
    const int tx = threadIdx.x, ty = threadIdx.y;
#pragma unroll
    for (int i = 0; i < 32; i += 8)
        s[ty + i][tx] = ib[(long)(t0 + ty + i) * DD + d0 + tx];
    __syncthreads();
#pragma unroll
    for (int i = 0; i < 32; i += 8) {
        float v = s[tx][ty + i];
        bf16 h = __float2bfloat16_rn(v);
        long o = (long)(d0 + ty + i) * TT + t0 + tx;
        oh_b[o] = h;
        ol_b[o] = __float2bfloat16_rn(v - __bfloat162float(h));
    }
}

__global__ void rowdot(const float* __restrict__ X, const float* __restrict__ w,
                       float* __restrict__ out, int ld, long nRows)
{
    long row = (long)blockIdx.x * (blockDim.x >> 5) + (threadIdx.x >> 5);
    if (row >= nRows) return;
    const int lane = threadIdx.x & 31;
    const float* x = X + row * ld;
    float s = 0.f;
    for (int k = lane; k < ld; k += 32) s += x[k] * w[k];
#pragma unroll
    for (int o = 16; o > 0; o >>= 1) s += __shfl_xor_sync(0xffffffffu, s, o);
    if (lane == 0) out[row] = s;
}

__global__ __launch_bounds__(128) void softmax_split(
    const float* __restrict__ sc, bf16* __restrict__ ah, bf16* __restrict__ al)
{
    __shared__ float smax[4];
    __shared__ float ssum[4];
    const long row = blockIdx.x;
    const float4* p = (const float4*)(sc + row * TT);
    const int tid = threadIdx.x;
    const int lane = tid & 31, warp = tid >> 5;

    float4 v = p[tid];
    float m = fmaxf(fmaxf(v.x, v.y), fmaxf(v.z, v.w));
#pragma unroll
    for (int o = 16; o > 0; o >>= 1) m = fmaxf(m, __shfl_xor_sync(0xffffffffu, m, o));
    if (lane == 0) smax[warp] = m;
    __syncthreads();
    m = fmaxf(fmaxf(smax[0], smax[1]), fmaxf(smax[2], smax[3]));

    v.x = expf(v.x - m); v.y = expf(v.y - m);
    v.z = expf(v.z - m); v.w = expf(v.w - m);
    float s = v.x + v.y + v.z + v.w;
#pragma unroll
    for (int o = 16; o > 0; o >>= 1) s += __shfl_xor_sync(0xffffffffu, s, o);
    if (lane == 0) ssum[warp] = s;
    __syncthreads();
    s = ssum[0] + ssum[1] + ssum[2] + ssum[3];

    const float inv = 1.0f / s;
    v.x *= inv; v.y *= inv; v.z *= inv; v.w *= inv;

    bf16 h0 = __float2bfloat16_rn(v.x), h1 = __float2bfloat16_rn(v.y);
    bf16 h2 = __float2bfloat16_rn(v.z), h3 = __float2bfloat16_rn(v.w);
    bf16 l0 = __float2bfloat16_rn(v.x - __bfloat162float(h0));
    bf16 l1 = __float2bfloat16_rn(v.y - __bfloat162float(h1));
    bf16 l2 = __float2bfloat16_rn(v.z - __bfloat162float(h2));
    bf16 l3 = __float2bfloat16_rn(v.w - __bfloat162float(h3));
    ((__nv_bfloat162*)(ah + row * TT))[2 * tid]     = __halves2bfloat162(h0, h1);
    ((__nv_bfloat162*)(ah + row * TT))[2 * tid + 1] = __halves2bfloat162(h2, h3);
    ((__nv_bfloat162*)(al + row * TT))[2 * tid]     = __halves2bfloat162(l0, l1);
    ((__nv_bfloat162*)(al + row * TT))[2 * tid + 1] = __halves2bfloat162(l2, l3);
}

// ---------------------------------------------------------------------------
extern "C" void kernel_launch(void* const* d_in, const int* in_sizes, int n_in,
                              void* d_out, int out_size)
{
    (void)in_sizes; (void)n_in; (void)out_size;
    const float* region = (const float*)d_in[0];
    const float* query  = (const float*)d_in[1];
    const float* Wr     = (const float*)d_in[2];
    const float* br     = (const float*)d_in[3];
    const float* Wq     = (const float*)d_in[4];
    const float* bq     = (const float*)d_in[5];
    const float* Ws     = (const float*)d_in[6];
    const float* bs     = (const float*)d_in[7];
    float* out = (float*)d_out;

    bf16 *region_h, *region_l, *query_h, *query_l;
    bf16 *Wr_h, *Wr_l, *Wq_h, *Wq_l, *Mt_h, *Mt_l, *Qp_h, *Qp_l;
    bf16 *qT_h, *qT_l, *attn_h, *attn_l;
    float *scores, *u, *v, *wrbq, *wqbr, *cptr;
    cudaGetSymbolAddress((void**)&region_h, g_region_h);
    cudaGetSymbolAddress((void**)&region_l, g_region_l);
    cudaGetSymbolAddress((void**)&query_h,  g_query_h);
    cudaGetSymbolAddress((void**)&query_l,  g_query_l);
    cudaGetSymbolAddress((void**)&Wr_h, g_Wr_h);
    cudaGetSymbolAddress((void**)&Wr_l, g_Wr_l);
    cudaGetSymbolAddress((void**)&Wq_h, g_Wq_h);
    cudaGetSymbolAddress((void**)&Wq_l, g_Wq_l);
    cudaGetSymbolAddress((void**)&Mt_h, g_Mt_h);
    cudaGetSymbolAddress((void**)&Mt_l, g_Mt_l);
    cudaGetSymbolAddress((void**)&Qp_h, g_Qp_h);
    cudaGetSymbolAddress((void**)&Qp_l, g_Qp_l);
    cudaGetSymbolAddress((void**)&qT_h, g_qT_h);
    cudaGetSymbolAddress((void**)&qT_l, g_qT_l);
    cudaGetSymbolAddress((void**)&attn_h, g_attn_h);
    cudaGetSymbolAddress((void**)&attn_l, g_attn_l);
    cudaGetSymbolAddress((void**)&scores, g_scores);
    cudaGetSymbolAddress((void**)&u,      g_u);
    cudaGetSymbolAddress((void**)&v,      g_v);
    cudaGetSymbolAddress((void**)&wrbq,   g_wrbq);
    cudaGetSymbolAddress((void**)&wqbr,   g_wqbr);
    cudaGetSymbolAddress((void**)&cptr,   g_c);

    cudaFuncSetAttribute(gemm3_bf16<1>, cudaFuncAttributeMaxDynamicSharedMemorySize, SMEM_GEMM);
    cudaFuncSetAttribute(gemm3_bf16<2>, cudaFuncAttributeMaxDynamicSharedMemorySize, SMEM_GEMM);
    cudaFuncSetAttribute(gemm3_bf16<3>, cudaFuncAttributeMaxDynamicSharedMemorySize, SMEM_GEMM);

    // weight prep
    split_bf16<<<(unsigned)(((long)DD*HH/4 + 255)/256), 256>>>(Wr, Wr_h, Wr_l, (long)DD*HH/4);
    split_bf16<<<(unsigned)(((long)DD*HH/4 + 255)/256), 256>>>(Wq, Wq_h, Wq_l, (long)DD*HH/4);
    rowdot<<<1, 32>>>(br, bq, cptr, HH, 1);                 // c = br.bq
    rowdot<<<DD/8, 256>>>(Wr, bq, wrbq, HH, DD);            // wrbq = Wr @ bq
    rowdot<<<DD/8, 256>>>(Wq, br, wqbr, HH, DD);            // wqbr = Wq @ br

    // fused input prep (split + dots + out init)
    prep_query <<<BB*TT, 256>>>(query, wqbr, query_h, query_l, v);
    prep_region<<<BB*RR, 256>>>(region, wrbq, cptr, Ws, bs, region_h, region_l, u, out);
    transpose_split<<<dim3(DD/32, TT/32, BB), dim3(32, 8)>>>(query, qT_h, qT_l);

    // 1) Mt2 = Wr @ Wq^T  (split out)  M=N=1024, K=1024
    gemm3_bf16<1><<<dim3(8, 8, 1), 128, SMEM_GEMM>>>(
        Wr_h, Wr_l, Wq_h, Wq_l, nullptr, Mt_h, Mt_l, nullptr, nullptr,
        nullptr, nullptr, nullptr,
        HH, HH, HH, DD, 0, 0, 0, 0, 0);

    // 2) Qp[b] = query[b] @ Mt2^T  (split out)  M=512, N=1024, K=1024
    gemm3_bf16<1><<<dim3(8, 4, BB), 128, SMEM_GEMM>>>(
        query_h, query_l, Mt_h, Mt_l, nullptr, Qp_h, Qp_l, nullptr, nullptr,
        nullptr, nullptr, nullptr,
        DD, DD, DD, DD, (long)TT*DD, 0, (long)TT*DD, 0, 0);

    // 3) scores[b] = region[b] @ Qp[b]^T + u + v   M=1024, N=512, K=1024
    gemm3_bf16<2><<<dim3(4, 8, BB), 128, SMEM_GEMM>>>(
        region_h, region_l, Qp_h, Qp_l, scores, nullptr, nullptr, u, v,
        nullptr, nullptr, nullptr,
        DD, DD, DD, TT, (long)RR*DD, (long)TT*DD, (long)RR*TT, RR, TT);

    // 4) softmax -> attn hi/lo
    softmax_split<<<BB*RR, 128>>>(scores, attn_h, attn_l);

    // 5) att[b] = attn[b] @ queryT[b]^T, fused scorer epilogue (atomicAdd to out)
    gemm3_bf16<3><<<dim3(8, 8, BB), 128, SMEM_GEMM>>>(
        attn_h, attn_l, qT_h, qT_l, nullptr, nullptr, nullptr, nullptr, nullptr,
        region, Ws, out,
        TT, TT, TT, DD, (long)RR*TT, (long)DD*TT, 0, 0, 0);
}

// round 9
// speedup vs baseline: 3.6707x; 1.0902x over previous
#include <cuda_runtime.h>
#include <cuda_bf16.h>
#include <cstdint>

#define BB 16
#define RR 1024
#define TT 512
#define DD 1024
#define HH 1024

typedef __nv_bfloat16 bf16;

// ---------------------------------------------------------------------------
// Scratch (__device__ globals; allocation-free rule)
// ---------------------------------------------------------------------------
__device__ bf16 g_region_h[BB*RR*DD], g_region_l[BB*RR*DD];
__device__ bf16 g_query_h [BB*TT*DD], g_query_l [BB*TT*DD];
__device__ bf16 g_Wr_h[DD*HH], g_Wr_l[DD*HH];
__device__ bf16 g_Wq_h[DD*HH], g_Wq_l[DD*HH];
__device__ bf16 g_Mt_h[DD*DD], g_Mt_l[DD*DD];        // Mt2 = Wr @ Wq^T
__device__ bf16 g_Qp_h[BB*TT*DD], g_Qp_l[BB*TT*DD];  // Qp = query @ Mt2^T
__device__ bf16 g_qT_h[BB*DD*TT], g_qT_l[BB*DD*TT];  // query^T [B][D][T]
__device__ bf16 g_attn_e[BB*RR*TT];                  // unnormalized exp (bf16)
__device__ float g_scores[BB*RR*TT];
__device__ float g_invden[BB*RR];
__device__ float g_u[BB*RR];
__device__ float g_v[BB*TT];
__device__ float g_wrbq[DD];
__device__ float g_wqbr[DD];
__device__ float g_c[1];

// ---------------------------------------------------------------------------
// PTX helpers (sm_80-compatible; compiles for compute_103 virtual arch)
// ---------------------------------------------------------------------------
__device__ __forceinline__ uint32_t smem_u32(const void* p) {
    uint32_t a;
    asm("{ .reg .u64 t; cvta.to.shared.u64 t, %1; cvt.u32.u64 %0, t; }" : "=r"(a) : "l"(p));
    return a;
}
#define CP_ASYNC16(dst, src) \
    asm volatile("cp.async.cg.shared.global [%0], [%1], 16;" :: "r"(dst), "l"(src))
#define CP_COMMIT() asm volatile("cp.async.commit_group;" ::: "memory")
#define CP_WAIT2()  asm volatile("cp.async.wait_group 2;" ::: "memory")
#define CP_WAIT1()  asm volatile("cp.async.wait_group 1;" ::: "memory")
#define CP_WAIT0()  asm volatile("cp.async.wait_group 0;" ::: "memory")

__device__ __forceinline__ void ldsm4(uint32_t* r, uint32_t addr) {
    asm volatile("ldmatrix.sync.aligned.m8n8.x4.shared.b16 {%0,%1,%2,%3}, [%4];"
                 : "=r"(r[0]), "=r"(r[1]), "=r"(r[2]), "=r"(r[3]) : "r"(addr));
}
__device__ __forceinline__ void mma16816(float* d, const uint32_t* a, const uint32_t* b) {
    asm volatile("mma.sync.aligned.m16n8k16.row.col.f32.bf16.bf16.f32 "
                 "{%0,%1,%2,%3}, {%4,%5,%6,%7}, {%8,%9}, {%0,%1,%2,%3};"
                 : "+f"(d[0]), "+f"(d[1]), "+f"(d[2]), "+f"(d[3])
                 : "r"(a[0]), "r"(a[1]), "r"(a[2]), "r"(a[3]), "r"(b[0]), "r"(b[1]));
}

// ---------------------------------------------------------------------------
// bf16 multi-phase GEMM (NT): C = sum over NPH phases.
//   NPH=3: { Ah*Bh, Ah*Bl, Al*Bh }   (bf16x3 error-compensated)
//   NPH=2: { Ah*Bh, Ah*Bl }          (A unsplit, B split)
// Block 128x128, BK=32, 4 warps (64x64 warp tile), 4-stage cp.async.
// EPI: 1 = bf16 hi/lo split store; 2 = fp32 + u[m] + v[n];
//      3 = fused scorer: atomicAdd out[r] += invden[r]*sum_c C*(Ws2+region*Ws3)
// ---------------------------------------------------------------------------
#define STAGE_B 20480
#define NSTAGE  4
#define SMEM_GEMM (NSTAGE * STAGE_B)   // 80 KB dynamic

template <int EPI, int NPH>
__global__ __launch_bounds__(128, 2) void gemm3_bf16(
    const bf16* __restrict__ Ah, const bf16* __restrict__ Al,
    const bf16* __restrict__ Bh, const bf16* __restrict__ Bl,
    float* __restrict__ Cf, bf16* __restrict__ Chi, bf16* __restrict__ Clo,
    const float* __restrict__ uvec, const float* __restrict__ vvec,
    const float* __restrict__ regionF, const float* __restrict__ WsP,
    float* __restrict__ outP,
    int Kbase, int lda, int ldb, int ldc,
    long sA, long sB, long sC, int uStr, int vStr)
{
    extern __shared__ __align__(16) uint8_t smem_raw[];
    const int tid = threadIdx.x;
    const int wid = tid >> 5, l = tid & 31;
    const int wm = wid >> 1, wn = wid & 1;
    const int blockM = blockIdx.y * 128, blockN = blockIdx.x * 128;
    const int z = blockIdx.z;

    Ah += (long)z * sA;  Al += (long)z * sA;
    Bh += (long)z * sB;  Bl += (long)z * sB;

    const uint32_t smBase = smem_u32(smem_raw);
    const int cpb = Kbase / 32;
    const int NK  = NPH * cpb;

    const uint32_t aF = smBase +
        (uint32_t)((wm * 64 + (l & 15)) * 80 + ((l >> 4) * 16));
    const int bn = (l & 7) + ((l & 16) >> 1);
    const uint32_t bF = smBase + 10240u +
        (uint32_t)((wn * 64 + bn) * 80 + (((l >> 3) & 1) * 16));

    float acc[4][8][4];
#pragma unroll
    for (int i = 0; i < 4; i++)
#pragma unroll
        for (int j = 0; j < 8; j++)
#pragma unroll
            for (int q = 0; q < 4; q++) acc[i][j][q] = 0.f;

    const int lr = tid >> 2, lj = tid & 3;

    auto load_stage = [&](int stage, int kb) {
        const int ph  = kb / cpb;
        const int kbl = kb - ph * cpb;
        const bf16* Ap = (NPH == 3 && ph == 2) ? Al : Ah;
        const bf16* Bp = (ph == 1) ? Bl : Bh;
        const int k0 = kbl * 32;
        const uint32_t sa = smBase + stage * STAGE_B;
        const uint32_t sb = sa + 10240u;
#pragma unroll
        for (int it = 0; it < 4; it++) {
            const int rr = lr + it * 32;
            const bf16* ga = Ap + (long)(blockM + rr) * lda + k0 + lj * 8;
            CP_ASYNC16(sa + (uint32_t)(rr * 80 + lj * 16), ga);
            const bf16* gb = Bp + (long)(blockN + rr) * ldb + k0 + lj * 8;
            CP_ASYNC16(sb + (uint32_t)(rr * 80 + lj * 16), gb);
        }
        CP_COMMIT();
    };

    load_stage(0, 0);
    load_stage(1, 1);
    load_stage(2, 2);

    for (int kb = 0; kb < NK; kb++) {
        if (kb < NK - 2)       CP_WAIT2();
        else if (kb == NK - 2) CP_WAIT1();
        else                   CP_WAIT0();
        __syncthreads();
        if (kb + 3 < NK) load_stage((kb + 3) & 3, kb + 3);

        const uint32_t so = (uint32_t)(kb & 3) * STAGE_B;
#pragma unroll
        for (int ks = 0; ks < 2; ks++) {
            uint32_t af[4][4], bfr[4][4];
#pragma unroll
            for (int i = 0; i < 4; i++)
                ldsm4(af[i], aF + so + (uint32_t)(i * (16 * 80) + ks * 32));
#pragma unroll
            for (int j = 0; j < 4; j++)
                ldsm4(bfr[j], bF + so + (uint32_t)(j * (16 * 80) + ks * 32));
#pragma unroll
            for (int i = 0; i < 4; i++)
#pragma unroll
                for (int j = 0; j < 4; j++) {
                    mma16816(acc[i][2 * j],     af[i], &bfr[j][0]);
                    mma16816(acc[i][2 * j + 1], af[i], &bfr[j][2]);
                }
        }
    }

    // ---- epilogue ----
    const int gid = l >> 2, tig = l & 3;
#pragma unroll
    for (int i = 0; i < 4; i++) {
        const int r0g = blockM + wm * 64 + 16 * i + gid;
        const int r1g = r0g + 8;
        float um0 = 0.f, um1 = 0.f;
        if (EPI == 2 || EPI == 3) {
            um0 = uvec[(long)z * uStr + r0g];
            um1 = uvec[(long)z * uStr + r1g];
        }
        float part0 = 0.f, part1 = 0.f;
#pragma unroll
        for (int jj = 0; jj < 8; jj++) {
            const int c0 = blockN + wn * 64 + 8 * jj + 2 * tig;
            float x0 = acc[i][jj][0], x1 = acc[i][jj][1];
            float x2 = acc[i][jj][2], x3 = acc[i][jj][3];
            if (EPI == 2) {
                float2 vv = *(const float2*)&vvec[(long)z * vStr + c0];
                x0 += um0 + vv.x;  x1 += um0 + vv.y;
                x2 += um1 + vv.x;  x3 += um1 + vv.y;
                float* base = Cf + (long)z * sC;
                *(float2*)&base[(long)r0g * ldc + c0] = make_float2(x0, x1);
                *(float2*)&base[(long)r1g * ldc + c0] = make_float2(x2, x3);
            } else if (EPI == 1) {
                bf16 h0 = __float2bfloat16_rn(x0), h1 = __float2bfloat16_rn(x1);
                bf16 h2 = __float2bfloat16_rn(x2), h3 = __float2bfloat16_rn(x3);
                bf16 l0 = __float2bfloat16_rn(x0 - __bfloat162float(h0));
                bf16 l1 = __float2bfloat16_rn(x1 - __bfloat162float(h1));
                bf16 l2 = __float2bfloat16_rn(x2 - __bfloat162float(h2));
                bf16 l3 = __float2bfloat16_rn(x3 - __bfloat162float(h3));
                bf16* bh = Chi + (long)z * sC;
                bf16* bl = Clo + (long)z * sC;
                *(__nv_bfloat162*)&bh[(long)r0g * ldc + c0] = __halves2bfloat162(h0, h1);
                *(__nv_bfloat162*)&bh[(long)r1g * ldc + c0] = __halves2bfloat162(h2, h3);
                *(__nv_bfloat162*)&bl[(long)r0g * ldc + c0] = __halves2bfloat162(l0, l1);
                *(__nv_bfloat162*)&bl[(long)r1g * ldc + c0] = __halves2bfloat162(l2, l3);
            } else { // EPI == 3 : fused scorer on UNNORMALIZED att
                const float* rgB = regionF + (long)z * RR * DD;
                float2 w2 = *(const float2*)&WsP[DD + c0];
                float2 w3 = *(const float2*)&WsP[2 * DD + c0];
                float2 r0v = *(const float2*)&rgB[(long)r0g * DD + c0];
                float2 r1v = *(const float2*)&rgB[(long)r1g * DD + c0];
                part0 += x0 * (w2.x + r0v.x * w3.x) + x1 * (w2.y + r0v.y * w3.y);
                part1 += x2 * (w2.x + r1v.x * w3.x) + x3 * (w2.y + r1v.y * w3.y);
            }
        }
        if (EPI == 3) {
            part0 += __shfl_xor_sync(0xffffffffu, part0, 1);
            part0 += __shfl_xor_sync(0xffffffffu, part0, 2);
            part1 += __shfl_xor_sync(0xffffffffu, part1, 1);
            part1 += __shfl_xor_sync(0xffffffffu, part1, 2);
            if (tig == 0) {
                atomicAdd(&outP[(long)z * RR + r0g], part0 * um0);  // um = invden
                atomicAdd(&outP[(long)z * RR + r1g], part1 * um1);
            }
        }
    }
}

// ---------------------------------------------------------------------------
// Prep kernels
// ---------------------------------------------------------------------------
__global__ __launch_bounds__(256) void split_bf16(
    const float* __restrict__ in, bf16* __restrict__ h, bf16* __restrict__ lo, long n4)
{
    long i = (long)blockIdx.x * blockDim.x + threadIdx.x;
    if (i >= n4) return;
    float4 v = ((const float4*)in)[i];
    bf16 h0 = __float2bfloat16_rn(v.x), h1 = __float2bfloat16_rn(v.y);
    bf16 h2 = __float2bfloat16_rn(v.z), h3 = __float2bfloat16_rn(v.w);
    bf16 l0 = __float2bfloat16_rn(v.x - __bfloat162float(h0));
    bf16 l1 = __float2bfloat16_rn(v.y - __bfloat162float(h1));
    bf16 l2 = __float2bfloat16_rn(v.z - __bfloat162float(h2));
    bf16 l3 = __float2bfloat16_rn(v.w - __bfloat162float(h3));
    ((__nv_bfloat162*)h )[2 * i]     = __halves2bfloat162(h0, h1);
    ((__nv_bfloat162*)h )[2 * i + 1] = __halves2bfloat162(h2, h3);
    ((__nv_bfloat162*)lo)[2 * i]     = __halves2bfloat162(l0, l1);
    ((__nv_bfloat162*)lo)[2 * i + 1] = __halves2bfloat162(l2, l3);
}

__global__ __launch_bounds__(256) void prep_region(
    const float* __restrict__ region, const float* __restrict__ wrbq,
    const float* __restrict__ cptr, const float* __restrict__ Ws,
    const float* __restrict__ bs,
    bf16* __restrict__ rh, bf16* __restrict__ rl,
    float* __restrict__ u, float* __restrict__ outp)
{
    __shared__ float redA[8], redB[8];
    const long row = blockIdx.x;
    const int tid = threadIdx.x, lane = tid & 31, warp = tid >> 5;

    float4 v = ((const float4*)(region + row * DD))[tid];
    bf16 h0 = __float2bfloat16_rn(v.x), h1 = __float2bfloat16_rn(v.y);
    bf16 h2 = __float2bfloat16_rn(v.z), h3 = __float2bfloat16_rn(v.w);
    bf16 l0 = __float2bfloat16_rn(v.x - __bfloat162float(h0));
    bf16 l1 = __float2bfloat16_rn(v.y - __bfloat162float(h1));
    bf16 l2 = __float2bfloat16_rn(v.z - __bfloat162float(h2));
    bf16 l3 = __float2bfloat16_rn(v.w - __bfloat162float(h3));
    ((__nv_bfloat162*)(rh + row * DD))[2 * tid]     = __halves2bfloat162(h0, h1);
    ((__nv_bfloat162*)(rh + row * DD))[2 * tid + 1] = __halves2bfloat162(h2, h3);
    ((__nv_bfloat162*)(rl + row * DD))[2 * tid]     = __halves2bfloat162(l0, l1);
    ((__nv_bfloat162*)(rl + row * DD))[2 * tid + 1] = __halves2bfloat162(l2, l3);

    float4 w  = ((const float4*)wrbq)[tid];
    float4 w1 = ((const float4*)Ws  )[tid];
    float du = v.x * w.x  + v.y * w.y  + v.z * w.z  + v.w * w.w;
    float dn = v.x * w1.x + v.y * w1.y + v.z * w1.z + v.w * w1.w;
#pragma unroll
    for (int o = 16; o > 0; o >>= 1) {
        du += __shfl_xor_sync(0xffffffffu, du, o);
        dn += __shfl_xor_sync(0xffffffffu, dn, o);
    }
    if (lane == 0) { redA[warp] = du; redB[warp] = dn; }
    __syncthreads();
    if (tid == 0) {
        float su = 0.f, sn = 0.f;
#pragma unroll
        for (int k = 0; k < 8; k++) { su += redA[k]; sn += redB[k]; }
        u[row]    = su + cptr[0];
        outp[row] = sn + bs[0];
    }
}

__global__ __launch_bounds__(256) void prep_query(
    const float* __restrict__ query, const float* __restrict__ wqbr,
    bf16* __restrict__ qh, bf16* __restrict__ ql, float* __restrict__ vvec)
{
    __shared__ float red[8];
    const long row = blockIdx.x;
    const int tid = threadIdx.x, lane = tid & 31, warp = tid >> 5;

    float4 v = ((const float4*)(query + row * DD))[tid];
    bf16 h0 = __float2bfloat16_rn(v.x), h1 = __float2bfloat16_rn(v.y);
    bf16 h2 = __float2bfloat16_rn(v.z), h3 = __float2bfloat16_rn(v.w);
    bf16 l0 = __float2bfloat16_rn(v.x - __bfloat162float(h0));
    bf16 l1 = __float2bfloat16_rn(v.y - __bfloat162float(h1));
    bf16 l2 = __float2bfloat16_rn(v.z - __bfloat162float(h2));
    bf16 l3 = __float2bfloat16_rn(v.w - __bfloat162float(h3));
    ((__nv_bfloat162*)(qh + row * DD))[2 * tid]     = __halves2bfloat162(h0, h1);
    ((__nv_bfloat162*)(qh + row * DD))[2 * tid + 1] = __halves2bfloat162(h2, h3);
    ((__nv_bfloat162*)(ql + row * DD))[2 * tid]     = __halves2bfloat162(l0, l1);
    ((__nv_bfloat162*)(ql + row * DD))[2 * tid + 1] = __halves2bfloat162(l2, l3);

    float4 w = ((const float4*)wqbr)[tid];
    float d = v.x * w.x + v.y * w.y + v.z * w.z + v.w * w.w;
#pragma unroll
    for (int o = 16; o > 0; o >>= 1) d += __shfl_xor_sync(0xffffffffu, d, o);
    if (lane == 0) red[warp] = d;
    __syncthreads();
    if (tid == 0) {
        float s = 0.f;
#pragma unroll
        for (int k = 0; k < 8; k++) s += red[k];
        vvec[row] = s;
    }
}

__global__ __launch_bounds__(256) void transpose_split(
    const float* __restrict__ in, bf16* __restrict__ oh, bf16* __restrict__ ol)
{
    __shared__ float s[32][33];
    const float* ib = in + (long)blockIdx.z * TT * DD;
    bf16* oh_b = oh + (long)blockIdx.z * DD * TT;
    bf16* ol_b = ol + (long)blockIdx.z * DD * TT;
    const int d0 = blockIdx.x * 32, t0 = blockIdx.y * 32;
    const int tx = threadIdx.x, ty = threadIdx.y;
#pragma unroll
    for (int i = 0; i < 32; i += 8)
        s[ty + i][tx] = ib[(long)(t0 + ty + i) * DD + d0 + tx];
    __syncthreads();
#pragma unroll
    for (int i = 0; i < 32; i += 8) {
        float v = s[tx][ty + i];
        bf16 h = __float2bfloat16_rn(v);
        long o = (long)(d0 + ty + i) * TT + t0 + tx;
        oh_b[o] = h;
        ol_b[o] = __float2bfloat16_rn(v - __bfloat162float(h));
    }
}

__global__ void rowdot(const float* __restrict__ X, const float* __restrict__ w,
                       float* __restrict__ out, int ld, long nRows)
{
    long row = (long)blockIdx.x * (blockDim.x >> 5) + (threadIdx.x >> 5);
    if (row >= nRows) return;
    const int lane = threadIdx.x & 31;
    const float* x = X + row * ld;
    float s = 0.f;
    for (int k = lane; k < ld; k += 32) s += x[k] * w[k];
#pragma unroll
    for (int o = 16; o > 0; o >>= 1) s += __shfl_xor_sync(0xffffffffu, s, o);
    if (lane == 0) out[row] = s;
}

// softmax numerator: exp(x - max) rounded to bf16; invden = 1/sum(rounded exp)
__global__ __launch_bounds__(128) void softmax_exp(
    const float* __restrict__ sc, bf16* __restrict__ ae, float* __restrict__ invden)
{
    __shared__ float smax[4];
    __shared__ float ssum[4];
    const long row = blockIdx.x;
    const float4* p = (const float4*)(sc + row * TT);
    const int tid = threadIdx.x;
    const int lane = tid & 31, warp = tid >> 5;

    float4 v = p[tid];
    float m = fmaxf(fmaxf(v.x, v.y), fmaxf(v.z, v.w));
#pragma unroll
    for (int o = 16; o > 0; o >>= 1) m = fmaxf(m, __shfl_xor_sync(0xffffffffu, m, o));
    if (lane == 0) smax[warp] = m;
    __syncthreads();
    m = fmaxf(fmaxf(smax[0], smax[1]), fmaxf(smax[2], smax[3]));

    // round exps to bf16 FIRST, then sum the rounded values (error cancellation)
    bf16 e0 = __float2bfloat16_rn(expf(v.x - m));
    bf16 e1 = __float2bfloat16_rn(expf(v.y - m));
    bf16 e2 = __float2bfloat16_rn(expf(v.z - m));
    bf16 e3 = __float2bfloat16_rn(expf(v.w - m));
    ((__nv_bfloat162*)(ae + row * TT))[2 * tid]     = __halves2bfloat162(e0, e1);
    ((__nv_bfloat162*)(ae + row * TT))[2 * tid + 1] = __halves2bfloat162(e2, e3);

    float s = __bfloat162float(e0) + __bfloat162float(e1)
            + __bfloat162float(e2) + __bfloat162float(e3);
#pragma unroll
    for (int o = 16; o > 0; o >>= 1) s += __shfl_xor_sync(0xffffffffu, s, o);
    if (lane == 0) ssum[warp] = s;
    __syncthreads();
    if (tid == 0)
        invden[row] = 1.0f / (ssum[0] + ssum[1] + ssum[2] + ssum[3]);
}

// ---------------------------------------------------------------------------
extern "C" void kernel_launch(void* const* d_in, const int* in_sizes, int n_in,
                              void* d_out, int out_size)
{
    (void)in_sizes; (void)n_in; (void)out_size;
    const float* region = (const float*)d_in[0];
    const float* query  = (const float*)d_in[1];
    const float* Wr     = (const float*)d_in[2];
    const float* br     = (const float*)d_in[3];
    const float* Wq     = (const float*)d_in[4];
    const float* bq     = (const float*)d_in[5];
    const float* Ws     = (const float*)d_in[6];
    const float* bs     = (const float*)d_in[7];
    float* out = (float*)d_out;

    bf16 *region_h, *region_l, *query_h, *query_l;
    bf16 *Wr_h, *Wr_l, *Wq_h, *Wq_l, *Mt_h, *Mt_l, *Qp_h, *Qp_l;
    bf16 *qT_h, *qT_l, *attn_e;
    float *scores, *invden, *u, *v, *wrbq, *wqbr, *cptr;
    cudaGetSymbolAddress((void**)&region_h, g_region_h);
    cudaGetSymbolAddress((void**)&region_l, g_region_l);
    cudaGetSymbolAddress((void**)&query_h,  g_query_h);
    cudaGetSymbolAddress((void**)&query_l,  g_query_l);
    cudaGetSymbolAddress((void**)&Wr_h, g_Wr_h);
    cudaGetSymbolAddress((void**)&Wr_l, g_Wr_l);
    cudaGetSymbolAddress((void**)&Wq_h, g_Wq_h);
    cudaGetSymbolAddress((void**)&Wq_l, g_Wq_l);
    cudaGetSymbolAddress((void**)&Mt_h, g_Mt_h);
    cudaGetSymbolAddress((void**)&Mt_l, g_Mt_l);
    cudaGetSymbolAddress((void**)&Qp_h, g_Qp_h);
    cudaGetSymbolAddress((void**)&Qp_l, g_Qp_l);
    cudaGetSymbolAddress((void**)&qT_h, g_qT_h);
    cudaGetSymbolAddress((void**)&qT_l, g_qT_l);
    cudaGetSymbolAddress((void**)&attn_e, g_attn_e);
    cudaGetSymbolAddress((void**)&scores, g_scores);
    cudaGetSymbolAddress((void**)&invden, g_invden);
    cudaGetSymbolAddress((void**)&u,      g_u);
    cudaGetSymbolAddress((void**)&v,      g_v);
    cudaGetSymbolAddress((void**)&wrbq,   g_wrbq);
    cudaGetSymbolAddress((void**)&wqbr,   g_wqbr);
    cudaGetSymbolAddress((void**)&cptr,   g_c);

    cudaFuncSetAttribute((const void*)gemm3_bf16<1,3>, cudaFuncAttributeMaxDynamicSharedMemorySize, SMEM_GEMM);
    cudaFuncSetAttribute((const void*)gemm3_bf16<2,3>, cudaFuncAttributeMaxDynamicSharedMemorySize, SMEM_GEMM);
    cudaFuncSetAttribute((const void*)gemm3_bf16<3,2>, cudaFuncAttributeMaxDynamicSharedMemorySize, SMEM_GEMM);

    // weight prep
    split_bf16<<<(unsigned)(((long)DD*HH/4 + 255)/256), 256>>>(Wr, Wr_h, Wr_l, (long)DD*HH/4);
    split_bf16<<<(unsigned)(((long)DD*HH/4 + 255)/256), 256>>>(Wq, Wq_h, Wq_l, (long)DD*HH/4);
    rowdot<<<1, 32>>>(br, bq, cptr, HH, 1);                 // c = br.bq
    rowdot<<<DD/8, 256>>>(Wr, bq, wrbq, HH, DD);            // wrbq = Wr @ bq
    rowdot<<<DD/8, 256>>>(Wq, br, wqbr, HH, DD);            // wqbr = Wq @ br

    // fused input prep
    prep_query <<<BB*TT, 256>>>(query, wqbr, query_h, query_l, v);
    prep_region<<<BB*RR, 256>>>(region, wrbq, cptr, Ws, bs, region_h, region_l, u, out);
    transpose_split<<<dim3(DD/32, TT/32, BB), dim3(32, 8)>>>(query, qT_h, qT_l);

    // 1) Mt2 = Wr @ Wq^T  (bf16x3, split out)
    gemm3_bf16<1,3><<<dim3(8, 8, 1), 128, SMEM_GEMM>>>(
        Wr_h, Wr_l, Wq_h, Wq_l, nullptr, Mt_h, Mt_l, nullptr, nullptr,
        nullptr, nullptr, nullptr,
        HH, HH, HH, DD, 0, 0, 0, 0, 0);

    // 2) Qp[b] = query[b] @ Mt2^T  (bf16x3, split out)
    gemm3_bf16<1,3><<<dim3(8, 4, BB), 128, SMEM_GEMM>>>(
        query_h, query_l, Mt_h, Mt_l, nullptr, Qp_h, Qp_l, nullptr, nullptr,
        nullptr, nullptr, nullptr,
        DD, DD, DD, DD, (long)TT*DD, 0, (long)TT*DD, 0, 0);

    // 3) scores[b] = region[b] @ Qp[b]^T + u + v  (bf16x3)
    gemm3_bf16<2,3><<<dim3(4, 8, BB), 128, SMEM_GEMM>>>(
        region_h, region_l, Qp_h, Qp_l, scores, nullptr, nullptr, u, v,
        nullptr, nullptr, nullptr,
        DD, DD, DD, TT, (long)RR*DD, (long)TT*DD, (long)RR*TT, RR, TT);

    // 4) softmax numerator -> bf16 exp + invden
    softmax_exp<<<BB*RR, 128>>>(scores, attn_e, invden);

    // 5) attU[b] @ queryT[b]^T  (2-phase: exp*q_hi, exp*q_lo), fused scorer
    //    epilogue normalizes by invden and atomicAdds into out
    gemm3_bf16<3,2><<<dim3(8, 8, BB), 128, SMEM_GEMM>>>(
        attn_e, attn_e, qT_h, qT_l, nullptr, nullptr, nullptr, invden, nullptr,
        region, Ws, out,
        TT, TT, TT, DD, (long)RR*TT, (long)DD*TT, 0, RR, 0);
}